// round 12
// baseline (speedup 1.0000x reference)
#include <cuda_runtime.h>
#include <cuda_fp16.h>

#define BATCH 128
#define DIN   512
#define HID   1024
#define G4    4096
#define STEPS 64
#define TOFF  55   // (128 - 64 - 9)

typedef unsigned int u32;

// ---------------- device scratch (no allocations allowed) -----------------
__device__ float  g_xproj[(size_t)STEPS * BATCH * G4];
__device__ __half g_h0hi[2][BATCH * HID], g_h0lo[2][BATCH * HID];
__device__ __half g_h1hi[2][BATCH * HID], g_h1lo[2][BATCH * HID];
__device__ float  g_c0[BATCH * HID];
__device__ __half g_xshi[(size_t)STEPS * BATCH * DIN];
__device__ __half g_xslo[(size_t)STEPS * BATCH * DIN];
__device__ uint4  g_whh0p[(size_t)512 * 64 * 32];
__device__ uint4  g_wih1p[(size_t)512 * 64 * 32];
__device__ uint4  g_whh1p[(size_t)512 * 64 * 32];
__device__ uint4  g_wih0p[(size_t)512 * 32 * 32];
__device__ u32    g_bar_count, g_bar_gen;

__device__ __forceinline__ float sigm(float x) { return 1.0f / (1.0f + expf(-x)); }
__device__ __forceinline__ u32 h2u(__half2 h) { return *(u32*)&h; }

__device__ __forceinline__ void mma_f16(float* d, const u32* a, const u32* b) {
    asm volatile("mma.sync.aligned.m16n8k16.row.col.f32.f16.f16.f32 "
        "{%0,%1,%2,%3},{%4,%5,%6,%7},{%8,%9},{%0,%1,%2,%3};"
        : "+f"(d[0]), "+f"(d[1]), "+f"(d[2]), "+f"(d[3])
        : "r"(a[0]), "r"(a[1]), "r"(a[2]), "r"(a[3]), "r"(b[0]), "r"(b[1]));
}
__device__ __forceinline__ u32 smem_u32(const void* p) {
    u32 a;
    asm("{ .reg .u64 t; cvta.to.shared.u64 t, %1; cvt.u32.u64 %0, t; }" : "=r"(a) : "l"(p));
    return a;
}
__device__ __forceinline__ void cpa16(u32 dst, const void* src) {
    asm volatile("cp.async.cg.shared.global [%0], [%1], 16;"
                 :: "r"(dst), "l"(__cvta_generic_to_global(src)) : "memory");
}
__device__ __forceinline__ void cpa_commit() {
    asm volatile("cp.async.commit_group;" ::: "memory");
}
template<int N> __device__ __forceinline__ void cpa_wait() {
    asm volatile("cp.async.wait_group %0;" :: "n"(N) : "memory");
}
__device__ __forceinline__ void ldm4(u32* r, u32 addr) {
    asm volatile("ldmatrix.sync.aligned.m8n8.x4.shared.b16 {%0,%1,%2,%3}, [%4];"
        : "=r"(r[0]), "=r"(r[1]), "=r"(r[2]), "=r"(r[3]) : "r"(addr));
}

// step-kernel smem: 4 stages of 53248 B (A 4 planes x 10240 | B 3 x 4096)
#define ST_SZ    53248
#define ST_B     40960
#define PS_TOTAL (4 * ST_SZ)

// xproj smem: 4 stages of 36864 B (Ahi 10240 | Alo 10240 | B 16384)
#define XP_ST    36864
#define XP_B     20480
#define XP_TOTAL (4 * XP_ST)

// ---------------- grid-wide software barrier (128 CTAs) --------------------
__device__ __forceinline__ void grid_barrier(int gen) {
    __syncthreads();
    if (threadIdx.x == 0) {
        __threadfence();
        u32 prev = atomicAdd(&g_bar_count, 1u);
        if (prev == (u32)(gen * 128 + 127)) {
            atomicExch(&g_bar_gen, (u32)(gen + 1));
        } else {
            u32 g;
            do {
                __nanosleep(64);
                asm volatile("ld.acquire.gpu.u32 %0, [%1];"
                             : "=r"(g) : "l"((const u32*)&g_bar_gen));
            } while (g <= (u32)gen);
        }
    }
    __syncthreads();
}

// ---------------- init states ----------------------------------------------
__global__ void init_states() {
    int i = blockIdx.x * blockDim.x + threadIdx.x;
    if (i == 0) { g_bar_count = 0u; g_bar_gen = 0u; }
    if (i < BATCH * HID) {
        __half z = __float2half(0.f);
        g_h0hi[0][i] = z; g_h0lo[0][i] = z; g_h0hi[1][i] = z; g_h0lo[1][i] = z;
        g_h1hi[0][i] = z; g_h1lo[0][i] = z; g_h1hi[1][i] = z; g_h1lo[1][i] = z;
        g_c0[i] = 0.f;
    }
}

// ---------------- packers (single launch) ----------------------------------
__device__ __forceinline__ void pack_one(
    const float* __restrict__ W, uint4* __restrict__ dst, int Kt, int idx)
{
    int lane = idx & 31;
    int rest = idx >> 5;
    int kt = rest % Kt, nt = rest / Kt;
    int K = Kt * 16;
    int n = nt * 8 + (lane >> 2);
    int k0 = kt * 16 + (lane & 3) * 2;
    const float* wr = W + (size_t)n * K + k0;
    float w00 = wr[0], w01 = wr[1], w10 = wr[8], w11 = wr[9];
    __half h00 = __float2half_rn(w00), h01 = __float2half_rn(w01);
    __half h10 = __float2half_rn(w10), h11 = __float2half_rn(w11);
    uint4 v;
    v.x = h2u(__halves2half2(h00, h01));
    v.y = h2u(__halves2half2(h10, h11));
    v.z = h2u(__halves2half2(__float2half_rn(w00 - __half2float(h00)),
                             __float2half_rn(w01 - __half2float(h01))));
    v.w = h2u(__halves2half2(__float2half_rn(w10 - __half2float(h10)),
                             __float2half_rn(w11 - __half2float(h11))));
    dst[idx] = v;
}
__device__ __forceinline__ void pack_xs_one(const float* __restrict__ xs, int idx) {
    int k = idx & 511;
    int b = (idx >> 9) & 127;
    int t = idx >> 16;
    float x = xs[((size_t)(b * 128 + TOFF + t)) * DIN + k];
    __half h = __float2half_rn(x);
    g_xshi[idx] = h;
    g_xslo[idx] = __float2half_rn(x - __half2float(h));
}
#define PACK_N64 (512 * 64 * 32)
#define PACK_N32 (512 * 32 * 32)
#define PACK_XS  (STEPS * BATCH * DIN)
#define PACK_TOTAL (3 * PACK_N64 + PACK_N32 + PACK_XS)
__global__ void pack_all(const float* __restrict__ Whh0, const float* __restrict__ Wih1,
                         const float* __restrict__ Whh1, const float* __restrict__ Wih0,
                         const float* __restrict__ xs) {
    int idx = blockIdx.x * 256 + threadIdx.x;
    if (idx < PACK_N64)                          pack_one(Whh0, g_whh0p, 64, idx);
    else if (idx < 2 * PACK_N64)                 pack_one(Wih1, g_wih1p, 64, idx - PACK_N64);
    else if (idx < 3 * PACK_N64)                 pack_one(Whh1, g_whh1p, 64, idx - 2 * PACK_N64);
    else if (idx < 3 * PACK_N64 + PACK_N32)      pack_one(Wih0, g_wih0p, 32, idx - 3 * PACK_N64);
    else                                         pack_xs_one(xs, idx - 3 * PACK_N64 - PACK_N32);
}

// ===========================================================================
// xproj v3 (round-11 validated, unchanged)
// ===========================================================================
__global__ void __launch_bounds__(512) xproj_kernel(
    const float* __restrict__ bih0, const float* __restrict__ bhh0)
{
    extern __shared__ char smem[];
    const int tid = threadIdx.x;
    const int nbx = blockIdx.x;
    const int mb  = blockIdx.y;
    const int w = tid >> 5, lane = tid & 31, qr = lane >> 2, qc = lane & 3;
    const int wg2 = w & 3, nq = w >> 2;
    const u32 sb = smem_u32(smem);

    float acc[2][4][4];
#pragma unroll
    for (int i = 0; i < 2; i++)
#pragma unroll
        for (int j = 0; j < 4; j++)
#pragma unroll
            for (int k = 0; k < 4; k++) acc[i][j][k] = 0.f;

    const bool doA = (tid < 256);
    u32 adst[4]; const __half* asrc[4];
#pragma unroll
    for (int i = 0; i < 4; i++) {
        int idx = (tid & 255) + i * 256;
        int plane = idx >> 9, row = (idx >> 2) & 127, seg = idx & 3;
        adst[i] = sb + plane * 10240 + row * 80 + seg * 16;
        const __half* base = plane ? g_xslo : g_xshi;
        asrc[i] = base + (size_t)(mb * 128 + row) * DIN + seg * 8;
    }
    u32 bdst[4]; size_t bsrc[4];
#pragma unroll
    for (int i = 0; i < 4; i++) {
        int idx = (tid & 255) + i * 256;
        int f = idx >> 5, ln = idx & 31;
        bdst[i] = sb + XP_B + ((u32)idx << 4);
        bsrc[i] = ((size_t)(nbx * 16 + (f >> 1)) * 32 + (f & 1)) * 32 + ln;
    }
    u32 aF[2];
#pragma unroll
    for (int mt = 0; mt < 2; mt++)
        aF[mt] = sb + ((wg2 * 2 + mt) * 16 + (lane & 15)) * 80 + ((lane >> 4) * 16);

    auto issue = [&](int kk) {
        const u32 soff = (u32)(kk & 3) * XP_ST;
        if (doA) {
#pragma unroll
            for (int i = 0; i < 4; i++)
                cpa16(adst[i] + soff, asrc[i] + kk * 32);
        } else {
#pragma unroll
            for (int i = 0; i < 4; i++)
                cpa16(bdst[i] + soff, g_wih0p + bsrc[i] + (size_t)kk * 64);
        }
    };

    issue(0); cpa_commit();
    issue(1); cpa_commit();

#pragma unroll 1
    for (int kk = 0; kk < 16; kk += 2) {
        cpa_wait<0>();
        __syncthreads();
        if (kk + 2 < 16) {
            issue(kk + 2); cpa_commit();
            issue(kk + 3); cpa_commit();
        }
#pragma unroll
        for (int half = 0; half < 2; half++) {
            const int s = (kk + half) & 3;
            const uint4* bst = (const uint4*)(smem + (size_t)s * XP_ST + XP_B);
#pragma unroll
            for (int sub = 0; sub < 2; sub++) {
                u32 ah[2][4], al[2][4];
#pragma unroll
                for (int mt = 0; mt < 2; mt++) {
                    ldm4(ah[mt], aF[mt] + (u32)s * XP_ST + sub * 32);
                    ldm4(al[mt], aF[mt] + (u32)s * XP_ST + 10240 + sub * 32);
                }
#pragma unroll
                for (int j = 0; j < 4; j++) {
                    int f = (nq * 4 + j) * 2 + sub;
                    uint4 bp = bst[f * 32 + lane];
                    u32 bh[2] = {bp.x, bp.y}, bl[2] = {bp.z, bp.w};
#pragma unroll
                    for (int mt = 0; mt < 2; mt++) {
                        mma_f16(acc[mt][j], ah[mt], bh);
                        mma_f16(acc[mt][j], al[mt], bh);
                        mma_f16(acc[mt][j], ah[mt], bl);
                    }
                }
            }
        }
    }

#pragma unroll
    for (int mt = 0; mt < 2; mt++) {
        int rl = (wg2 * 2 + mt) * 16 + qr;
        size_t rowbase = ((size_t)mb * 128 + rl) * G4;
#pragma unroll
        for (int j = 0; j < 4; j++) {
            int col = nbx * 128 + (nq * 4 + j) * 8 + qc * 2;
            float bv0 = bih0[col] + bhh0[col];
            float bv1 = bih0[col + 1] + bhh0[col + 1];
            *(float2*)&g_xproj[rowbase + col] =
                make_float2(acc[mt][j][0] + bv0, acc[mt][j][1] + bv1);
            *(float2*)&g_xproj[rowbase + (size_t)8 * G4 + col] =
                make_float2(acc[mt][j][2] + bv0, acc[mt][j][3] + bv1);
        }
    }
}

// ===========================================================================
// Persistent fused-step kernel. Grid 128, 512 threads = 16 warps.
// mtp = w&3 -> mtile PAIR (rows mtp*32..+31); slot = w>>2:
//   slot0: h0(t+1)@Wih1, subs 0+1 (48 MMA/chunk) -> L1 part a + L1 epilogue
//   slot1: h1(t)  @Whh1, subs 0+1 (48)           -> publish L1 part b
//   slot2: h0(t+1)@Whh0, sub 0    (24)           -> L0 part a + L0 epilogue
//   slot3: h0(t+1)@Whh0, sub 1    (24)           -> publish L0 part b
// SMSP = mtp -> each scheduler hosts slots {0,1,2,3} = 144 MMA/chunk balanced.
// B fragments read ONCE per warp, reused across 2 mtiles (-33% crossbar).
// One 32KB partial combine per step. B prefetched across grid barrier.
// ===========================================================================
__global__ void __launch_bounds__(512) step_persist(
    const float* __restrict__ bih1, const float* __restrict__ bhh1)
{
    extern __shared__ char smem[];
    const int tid = threadIdx.x, bx = blockIdx.x;
    const int w = tid >> 5, lane = tid & 31, qr = lane >> 2, qc = lane & 3;
    const int mtp = w & 3, slot = w >> 2;
    const u32 sb = smem_u32(smem);
    const int n0 = bx * 8 + qc * 2;

    // ---- prologue: L0 step 0 (h0 = 0) on this CTA's 8 columns ----
    for (int i = tid; i < 128 * 8; i += 512) {
        int m = i >> 3, u = i & 7;
        int n = bx * 8 + u;
        const float* xr = g_xproj + (size_t)m * G4;
        float iv = xr[n], gv = xr[2048 + n], ov = xr[3072 + n];
        float cn = sigm(iv) * tanhf(gv);
        g_c0[m * HID + n] = cn;
        float h = sigm(ov) * tanhf(cn);
        __half hh = __float2half_rn(h);
        g_h0hi[1][m * HID + n] = hh;
        g_h0lo[1][m * HID + n] = __float2half_rn(h - __half2float(hh));
    }
    grid_barrier(0);

    // biases (L1) in regs (slot0 uses them)
    float bs[4][2];
#pragma unroll
    for (int g = 0; g < 4; g++) {
        bs[g][0] = bih1[g * 1024 + n0] + bhh1[g * 1024 + n0];
        bs[g][1] = bih1[g * 1024 + n0 + 1] + bhh1[g * 1024 + n0 + 1];
    }
    // c-state in regs: slot0 -> c1 (zeros), slot2 -> c0 (from prologue)
    float cr[2][4];
#pragma unroll
    for (int mt = 0; mt < 2; mt++)
#pragma unroll
        for (int r = 0; r < 4; r++) cr[mt][r] = 0.f;
    if (slot == 2) {
#pragma unroll
        for (int mt = 0; mt < 2; mt++)
#pragma unroll
            for (int rr = 0; rr < 2; rr++) {
                int m = (mtp * 2 + mt) * 16 + qr + rr * 8;
                cr[mt][rr * 2 + 0] = g_c0[m * HID + n0];
                cr[mt][rr * 2 + 1] = g_c0[m * HID + n0 + 1];
            }
    }

    // ---- invariant staging coords ----
    // A: all 512 threads, 4 cp16 each (4 planes x 128 rows x 4 segs)
    u32 adst[4]; u32 arow[4]; int aplane[4]; int aseg[4];
#pragma unroll
    for (int i = 0; i < 4; i++) {
        int idx = tid + i * 512;
        aplane[i] = idx >> 9;
        arow[i] = (idx >> 2) & 127;
        aseg[i] = idx & 3;
        adst[i] = sb + aplane[i] * 10240 + arow[i] * 80 + aseg[i] * 16;
    }
    // B: threads 0..255, 3 cp16 (one per matrix)
    const bool doB = (tid < 256);
    const int tw = (tid & 255) >> 5;
    const u32 bdst0 = sb + ST_B + ((tid & 255) << 4);
    const size_t bsrc0 = (((size_t)((tw >> 1) * 128 + bx)) * 64 + (tw & 1)) * 32 + lane;
    // A fragment bases for this warp's 2 mtiles (+ slot's A source)
    const u32 slotAoff = (slot == 1) ? 20480u : 0u;
    u32 aF[2];
#pragma unroll
    for (int mt = 0; mt < 2; mt++)
        aF[mt] = sb + slotAoff + ((mtp * 2 + mt) * 16 + (lane & 15)) * 80
               + ((lane >> 4) * 16);
    const int bmat = (slot == 0) ? 0 : (slot == 1) ? 256 : 512;

    float* red = (float*)smem;   // 32KB partial buffer (reuses stage 0 A area)

    auto issueB = [&](int kk) {
        const u32 soff = (u32)(kk & 3) * ST_SZ;
        cpa16(bdst0 + soff,        g_wih1p + bsrc0 + (size_t)kk * 64);
        cpa16(bdst0 + soff + 4096, g_whh1p + bsrc0 + (size_t)kk * 64);
        cpa16(bdst0 + soff + 8192, g_whh0p + bsrc0 + (size_t)kk * 64);
    };

    // initial B prefetch
    if (doB) {
        issueB(0); cpa_commit();
        issueB(1); cpa_commit();
    }

#pragma unroll 1
    for (int t = 0; t < STEPS; t++) {
        const int do_l0 = (t < STEPS - 1);
        const __half* Ap0 = g_h0hi[(t + 1) & 1];
        const __half* Ap1 = g_h0lo[(t + 1) & 1];
        const __half* Ap2 = g_h1hi[t & 1];
        const __half* Ap3 = g_h1lo[t & 1];

        float acc[2][4][4];
#pragma unroll
        for (int i = 0; i < 2; i++)
#pragma unroll
            for (int j = 0; j < 4; j++)
#pragma unroll
                for (int k = 0; k < 4; k++) acc[i][j][k] = 0.f;

        auto issueA = [&](int kk) {
            const u32 soff = (u32)(kk & 3) * ST_SZ;
#pragma unroll
            for (int i = 0; i < 4; i++) {
                const __half* base = (aplane[i] == 0) ? Ap0 :
                                     (aplane[i] == 1) ? Ap1 :
                                     (aplane[i] == 2) ? Ap2 : Ap3;
                cpa16(adst[i] + soff,
                      base + (size_t)arow[i] * HID + kk * 32 + aseg[i] * 8);
            }
        };

        issueA(0); cpa_commit();
        issueA(1); cpa_commit();

#pragma unroll 1
        for (int kk = 0; kk < 32; kk += 2) {
            cpa_wait<0>();
            __syncthreads();
            if (kk + 2 < 32) {
                issueA(kk + 2); if (doB) issueB(kk + 2); cpa_commit();
                issueA(kk + 3); if (doB) issueB(kk + 3); cpa_commit();
            }
#pragma unroll
            for (int half = 0; half < 2; half++) {
                const int s = (kk + half) & 3;
                const uint4* bst = (const uint4*)(smem + (size_t)s * ST_SZ + ST_B);
                const u32 soff = (u32)s * ST_SZ;
                if (slot < 2) {
#pragma unroll
                    for (int sub = 0; sub < 2; sub++) {
                        u32 ah[2][4], al[2][4];
#pragma unroll
                        for (int mt = 0; mt < 2; mt++) {
                            ldm4(ah[mt], aF[mt] + soff + sub * 32);
                            ldm4(al[mt], aF[mt] + soff + 10240 + sub * 32);
                        }
#pragma unroll
                        for (int nt = 0; nt < 4; nt++) {
                            uint4 bp = bst[bmat + (nt * 2 + sub) * 32 + lane];
                            u32 bh[2] = {bp.x, bp.y}, bl[2] = {bp.z, bp.w};
#pragma unroll
                            for (int mt = 0; mt < 2; mt++) {
                                mma_f16(acc[mt][nt], ah[mt], bh);
                                mma_f16(acc[mt][nt], al[mt], bh);
                                mma_f16(acc[mt][nt], ah[mt], bl);
                            }
                        }
                    }
                } else {
                    const int sub = slot - 2;
                    u32 ah[2][4], al[2][4];
#pragma unroll
                    for (int mt = 0; mt < 2; mt++) {
                        ldm4(ah[mt], aF[mt] + soff + sub * 32);
                        ldm4(al[mt], aF[mt] + soff + 10240 + sub * 32);
                    }
#pragma unroll
                    for (int nt = 0; nt < 4; nt++) {
                        uint4 bp = bst[512 + (nt * 2 + sub) * 32 + lane];
                        u32 bh[2] = {bp.x, bp.y}, bl[2] = {bp.z, bp.w};
#pragma unroll
                        for (int mt = 0; mt < 2; mt++) {
                            mma_f16(acc[mt][nt], ah[mt], bh);
                            mma_f16(acc[mt][nt], al[mt], bh);
                            mma_f16(acc[mt][nt], ah[mt], bl);
                        }
                    }
                }
            }
        }
        cpa_wait<0>();
        __syncthreads();

        // ---- publish partials: slot1 -> red[0..4096), slot3 -> red[4096..) ----
        if (slot == 1 || slot == 3) {
            const int off = (slot == 1) ? 0 : 4096;
#pragma unroll
            for (int mt = 0; mt < 2; mt++)
#pragma unroll
                for (int nt = 0; nt < 4; nt++)
#pragma unroll
                    for (int r = 0; r < 4; r++)
                        red[off + (((((mtp * 2 + mt) * 4 + nt) * 4 + r)) << 5) + lane]
                            = acc[mt][nt][r];
        }
        __syncthreads();

        if (slot == 0) {
            // ---- L1(t) epilogue (2 mtiles) ----
            __half* Hhi = g_h1hi[(t + 1) & 1];
            __half* Hlo = g_h1lo[(t + 1) & 1];
#pragma unroll
            for (int mt = 0; mt < 2; mt++) {
                const int mtg = mtp * 2 + mt;
#pragma unroll
                for (int rr = 0; rr < 2; rr++) {
                    int m = mtg * 16 + qr + rr * 8;
                    __half hh[2], hl[2];
#pragma unroll
                    for (int e = 0; e < 2; e++) {
                        int ri = rr * 2 + e;
                        float pI = red[((((mtg * 4 + 0) * 4 + ri)) << 5) + lane];
                        float pF = red[((((mtg * 4 + 1) * 4 + ri)) << 5) + lane];
                        float pG = red[((((mtg * 4 + 2) * 4 + ri)) << 5) + lane];
                        float pO = red[((((mtg * 4 + 3) * 4 + ri)) << 5) + lane];
                        float iv = acc[mt][0][ri] + pI + bs[0][e];
                        float fv = acc[mt][1][ri] + pF + bs[1][e];
                        float gv = acc[mt][2][ri] + pG + bs[2][e];
                        float ov = acc[mt][3][ri] + pO + bs[3][e];
                        float cn = sigm(fv) * cr[mt][ri] + sigm(iv) * tanhf(gv);
                        cr[mt][ri] = cn;
                        float h = sigm(ov) * tanhf(cn);
                        hh[e] = __float2half_rn(h);
                        hl[e] = __float2half_rn(h - __half2float(hh[e]));
                    }
                    *(__half2*)&Hhi[m * HID + n0] = __halves2half2(hh[0], hh[1]);
                    *(__half2*)&Hlo[m * HID + n0] = __halves2half2(hl[0], hl[1]);
                }
            }
        } else if (slot == 2 && do_l0) {
            // ---- L0(t+1) epilogue (2 mtiles) ----
            const float* xp = g_xproj + (size_t)(t + 1) * BATCH * G4;
            __half* Hhi = g_h0hi[t & 1];
            __half* Hlo = g_h0lo[t & 1];
#pragma unroll
            for (int mt = 0; mt < 2; mt++) {
                const int mtg = mtp * 2 + mt;
#pragma unroll
                for (int rr = 0; rr < 2; rr++) {
                    int m = mtg * 16 + qr + rr * 8;
                    const float* xr = xp + (size_t)m * G4 + n0;
                    float2 xi = *(const float2*)(xr);
                    float2 xf = *(const float2*)(xr + 1024);
                    float2 xg = *(const float2*)(xr + 2048);
                    float2 xo = *(const float2*)(xr + 3072);
                    __half hh[2], hl[2];
#pragma unroll
                    for (int e = 0; e < 2; e++) {
                        int ri = rr * 2 + e;
                        float pI = red[4096 + ((((mtg * 4 + 0) * 4 + ri)) << 5) + lane];
                        float pF = red[4096 + ((((mtg * 4 + 1) * 4 + ri)) << 5) + lane];
                        float pG = red[4096 + ((((mtg * 4 + 2) * 4 + ri)) << 5) + lane];
                        float pO = red[4096 + ((((mtg * 4 + 3) * 4 + ri)) << 5) + lane];
                        float iv = acc[mt][0][ri] + pI + (e ? xi.y : xi.x);
                        float fv = acc[mt][1][ri] + pF + (e ? xf.y : xf.x);
                        float gv = acc[mt][2][ri] + pG + (e ? xg.y : xg.x);
                        float ov = acc[mt][3][ri] + pO + (e ? xo.y : xo.x);
                        float cn = sigm(fv) * cr[mt][ri] + sigm(iv) * tanhf(gv);
                        cr[mt][ri] = cn;
                        float h = sigm(ov) * tanhf(cn);
                        hh[e] = __float2half_rn(h);
                        hl[e] = __float2half_rn(h - __half2float(hh[e]));
                    }
                    *(__half2*)&Hhi[m * HID + n0] = __halves2half2(hh[0], hh[1]);
                    *(__half2*)&Hlo[m * HID + n0] = __halves2half2(hl[0], hl[1]);
                }
            }
        }

        // prefetch next step's B (weights step-invariant)
        if (doB && t + 1 < STEPS) {
            issueB(0); cpa_commit();
            issueB(1); cpa_commit();
        }
        grid_barrier(t + 1);
    }
}

// ---------------- classifier (unchanged) ------------------------------------
__global__ void __launch_bounds__(256) classifier_kernel(
    const float* __restrict__ Wcls, const float* __restrict__ bcls,
    const float* __restrict__ dropu, float* __restrict__ out)
{
    int gw = (blockIdx.x * blockDim.x + threadIdx.x) >> 5;
    int lane = threadIdx.x & 31;
    int j = gw >> 5;
    int b0 = (gw & 31) * 4;
    const __half* hi = g_h1hi[0];
    const __half* lo = g_h1lo[0];

    float acc[4] = {0.f, 0.f, 0.f, 0.f};
#pragma unroll
    for (int it = 0; it < 8; ++it) {
        int h = it * 128 + lane * 4;
        float4 wv = *(const float4*)&Wcls[(size_t)j * HID + h];
#pragma unroll
        for (int bi = 0; bi < 4; ++bi) {
            int b = b0 + bi;
            int idx = b * HID + h;
            __half2 a0 = *(const __half2*)&hi[idx];
            __half2 a1 = *(const __half2*)&hi[idx + 2];
            __half2 c0 = *(const __half2*)&lo[idx];
            __half2 c1 = *(const __half2*)&lo[idx + 2];
            float2 f0 = __half22float2(a0), f1 = __half22float2(a1);
            float2 g0 = __half22float2(c0), g1 = __half22float2(c1);
            float x0 = f0.x + g0.x, x1 = f0.y + g0.y;
            float x2 = f1.x + g1.x, x3 = f1.y + g1.y;
            float4 u = *(const float4*)&dropu[(size_t)b * HID + h];
            acc[bi] += (u.x > 0.5f ? x0 : 0.f) * wv.x
                     + (u.y > 0.5f ? x1 : 0.f) * wv.y
                     + (u.z > 0.5f ? x2 : 0.f) * wv.z
                     + (u.w > 0.5f ? x3 : 0.f) * wv.w;
        }
    }
#pragma unroll
    for (int bi = 0; bi < 4; ++bi) {
        float v = acc[bi];
#pragma unroll
        for (int off = 16; off; off >>= 1)
            v += __shfl_xor_sync(0xffffffffu, v, off);
        if (lane == 0)
            out[(size_t)(b0 + bi) * 1000 + j] = 2.0f * v + bcls[j];
    }
}

// ---------------- launch ----------------------------------------------------
extern "C" void kernel_launch(void* const* d_in, const int* in_sizes, int n_in,
                              void* d_out, int out_size)
{
    const float* xs    = (const float*)d_in[0];
    const float* Wih0  = (const float*)d_in[1];
    const float* Whh0  = (const float*)d_in[2];
    const float* bih0  = (const float*)d_in[3];
    const float* bhh0  = (const float*)d_in[4];
    const float* Wih1  = (const float*)d_in[5];
    const float* Whh1  = (const float*)d_in[6];
    const float* bih1  = (const float*)d_in[7];
    const float* bhh1  = (const float*)d_in[8];
    const float* Wcls  = (const float*)d_in[9];
    const float* bcls  = (const float*)d_in[10];
    const float* dropu = (const float*)d_in[11];
    float* out = (float*)d_out;

    cudaFuncSetAttribute(step_persist, cudaFuncAttributeMaxDynamicSharedMemorySize, PS_TOTAL);
    cudaFuncSetAttribute(xproj_kernel, cudaFuncAttributeMaxDynamicSharedMemorySize, XP_TOTAL);

    init_states<<<(BATCH * HID + 255) / 256, 256>>>();
    pack_all<<<(PACK_TOTAL + 255) / 256, 256>>>(Whh0, Wih1, Whh1, Wih0, xs);
    xproj_kernel<<<dim3(32, 64), 512, XP_TOTAL>>>(bih0, bhh0);
    step_persist<<<128, 512, PS_TOTAL>>>(bih1, bhh1);
    classifier_kernel<<<4000, 256>>>(Wcls, bcls, dropu, out);
}

// round 13
// speedup vs baseline: 1.1043x; 1.1043x over previous
#include <cuda_runtime.h>
#include <cuda_fp16.h>

#define BATCH 128
#define DIN   512
#define HID   1024
#define G4    4096
#define STEPS 64
#define TOFF  55   // (128 - 64 - 9)

typedef unsigned int u32;

// ---------------- device scratch (no allocations allowed) -----------------
__device__ float  g_xproj[(size_t)STEPS * BATCH * G4];
__device__ __half g_h0hi[2][BATCH * HID], g_h0lo[2][BATCH * HID];
__device__ __half g_h1hi[2][BATCH * HID], g_h1lo[2][BATCH * HID];
__device__ float  g_c0[BATCH * HID];
__device__ __half g_xshi[(size_t)STEPS * BATCH * DIN];   // xs split, [t][b][k]
__device__ __half g_xslo[(size_t)STEPS * BATCH * DIN];
__device__ uint4  g_whh0p[(size_t)512 * 64 * 32];
__device__ uint4  g_wih1p[(size_t)512 * 64 * 32];
__device__ uint4  g_whh1p[(size_t)512 * 64 * 32];
__device__ uint4  g_wih0p[(size_t)512 * 32 * 32];
__device__ u32    g_bar_count, g_bar_gen;

__device__ __forceinline__ float sigm(float x) { return 1.0f / (1.0f + expf(-x)); }
__device__ __forceinline__ u32 h2u(__half2 h) { return *(u32*)&h; }

__device__ __forceinline__ void mma_f16(float* d, const u32* a, const u32* b) {
    asm volatile("mma.sync.aligned.m16n8k16.row.col.f32.f16.f16.f32 "
        "{%0,%1,%2,%3},{%4,%5,%6,%7},{%8,%9},{%0,%1,%2,%3};"
        : "+f"(d[0]), "+f"(d[1]), "+f"(d[2]), "+f"(d[3])
        : "r"(a[0]), "r"(a[1]), "r"(a[2]), "r"(a[3]), "r"(b[0]), "r"(b[1]));
}
__device__ __forceinline__ u32 smem_u32(const void* p) {
    u32 a;
    asm("{ .reg .u64 t; cvta.to.shared.u64 t, %1; cvt.u32.u64 %0, t; }" : "=r"(a) : "l"(p));
    return a;
}
__device__ __forceinline__ void cpa16(u32 dst, const void* src) {
    asm volatile("cp.async.cg.shared.global [%0], [%1], 16;"
                 :: "r"(dst), "l"(__cvta_generic_to_global(src)) : "memory");
}
__device__ __forceinline__ void cpa_commit() {
    asm volatile("cp.async.commit_group;" ::: "memory");
}
template<int N> __device__ __forceinline__ void cpa_wait() {
    asm volatile("cp.async.wait_group %0;" :: "n"(N) : "memory");
}
__device__ __forceinline__ void ldm4(u32* r, u32 addr) {
    asm volatile("ldmatrix.sync.aligned.m8n8.x4.shared.b16 {%0,%1,%2,%3}, [%4];"
        : "=r"(r[0]), "=r"(r[1]), "=r"(r[2]), "=r"(r[3]) : "r"(addr));
}

// step-kernel smem: 4 stages of 53248 B
#define ST_SZ    53248
#define ST_B     40960
#define PS_TOTAL (4 * ST_SZ)

// xproj smem: 4 stages of 36864 B (Ahi 10240 | Alo 10240 | B 16384)
#define XP_ST    36864
#define XP_B     20480
#define XP_TOTAL (4 * XP_ST)

// ---------------- grid-wide software barrier (128 CTAs) --------------------
__device__ __forceinline__ void grid_barrier(int gen) {
    __syncthreads();
    if (threadIdx.x == 0) {
        __threadfence();
        u32 prev = atomicAdd(&g_bar_count, 1u);
        if (prev == (u32)(gen * 128 + 127)) {
            atomicExch(&g_bar_gen, (u32)(gen + 1));
        } else {
            u32 g;
            do {
                __nanosleep(64);
                asm volatile("ld.acquire.gpu.u32 %0, [%1];"
                             : "=r"(g) : "l"((const u32*)&g_bar_gen));
            } while (g <= (u32)gen);
        }
    }
    __syncthreads();
}

// ---------------- init states ----------------------------------------------
__global__ void init_states() {
    int i = blockIdx.x * blockDim.x + threadIdx.x;
    if (i == 0) { g_bar_count = 0u; g_bar_gen = 0u; }
    if (i < BATCH * HID) {
        __half z = __float2half(0.f);
        g_h0hi[0][i] = z; g_h0lo[0][i] = z; g_h0hi[1][i] = z; g_h0lo[1][i] = z;
        g_h1hi[0][i] = z; g_h1lo[0][i] = z; g_h1hi[1][i] = z; g_h1lo[1][i] = z;
        g_c0[i] = 0.f;
    }
}

// ---------------- packers (single launch) ----------------------------------
__device__ __forceinline__ void pack_one(
    const float* __restrict__ W, uint4* __restrict__ dst, int Kt, int idx)
{
    int lane = idx & 31;
    int rest = idx >> 5;
    int kt = rest % Kt, nt = rest / Kt;
    int K = Kt * 16;
    int n = nt * 8 + (lane >> 2);
    int k0 = kt * 16 + (lane & 3) * 2;
    const float* wr = W + (size_t)n * K + k0;
    float w00 = wr[0], w01 = wr[1], w10 = wr[8], w11 = wr[9];
    __half h00 = __float2half_rn(w00), h01 = __float2half_rn(w01);
    __half h10 = __float2half_rn(w10), h11 = __float2half_rn(w11);
    uint4 v;
    v.x = h2u(__halves2half2(h00, h01));
    v.y = h2u(__halves2half2(h10, h11));
    v.z = h2u(__halves2half2(__float2half_rn(w00 - __half2float(h00)),
                             __float2half_rn(w01 - __half2float(h01))));
    v.w = h2u(__halves2half2(__float2half_rn(w10 - __half2float(h10)),
                             __float2half_rn(w11 - __half2float(h11))));
    dst[idx] = v;
}
__device__ __forceinline__ void pack_xs_one(const float* __restrict__ xs, int idx) {
    int k = idx & 511;
    int b = (idx >> 9) & 127;
    int t = idx >> 16;
    float x = xs[((size_t)(b * 128 + TOFF + t)) * DIN + k];
    __half h = __float2half_rn(x);
    g_xshi[idx] = h;
    g_xslo[idx] = __float2half_rn(x - __half2float(h));
}
#define PACK_N64 (512 * 64 * 32)
#define PACK_N32 (512 * 32 * 32)
#define PACK_XS  (STEPS * BATCH * DIN)
#define PACK_TOTAL (3 * PACK_N64 + PACK_N32 + PACK_XS)
__global__ void pack_all(const float* __restrict__ Whh0, const float* __restrict__ Wih1,
                         const float* __restrict__ Whh1, const float* __restrict__ Wih0,
                         const float* __restrict__ xs) {
    int idx = blockIdx.x * 256 + threadIdx.x;
    if (idx < PACK_N64)                          pack_one(Whh0, g_whh0p, 64, idx);
    else if (idx < 2 * PACK_N64)                 pack_one(Wih1, g_wih1p, 64, idx - PACK_N64);
    else if (idx < 3 * PACK_N64)                 pack_one(Whh1, g_whh1p, 64, idx - 2 * PACK_N64);
    else if (idx < 3 * PACK_N64 + PACK_N32)      pack_one(Wih0, g_wih0p, 32, idx - 3 * PACK_N64);
    else                                         pack_xs_one(xs, idx - 3 * PACK_N64 - PACK_N32);
}

// ===========================================================================
// xproj v3 (round-11 validated, 3-limb, unchanged)
// ===========================================================================
__global__ void __launch_bounds__(512) xproj_kernel(
    const float* __restrict__ bih0, const float* __restrict__ bhh0)
{
    extern __shared__ char smem[];
    const int tid = threadIdx.x;
    const int nbx = blockIdx.x;
    const int mb  = blockIdx.y;
    const int w = tid >> 5, lane = tid & 31, qr = lane >> 2, qc = lane & 3;
    const int wg2 = w & 3, nq = w >> 2;
    const u32 sb = smem_u32(smem);

    float acc[2][4][4];
#pragma unroll
    for (int i = 0; i < 2; i++)
#pragma unroll
        for (int j = 0; j < 4; j++)
#pragma unroll
            for (int k = 0; k < 4; k++) acc[i][j][k] = 0.f;

    const bool doA = (tid < 256);
    u32 adst[4]; const __half* asrc[4];
#pragma unroll
    for (int i = 0; i < 4; i++) {
        int idx = (tid & 255) + i * 256;
        int plane = idx >> 9, row = (idx >> 2) & 127, seg = idx & 3;
        adst[i] = sb + plane * 10240 + row * 80 + seg * 16;
        const __half* base = plane ? g_xslo : g_xshi;
        asrc[i] = base + (size_t)(mb * 128 + row) * DIN + seg * 8;
    }
    u32 bdst[4]; size_t bsrc[4];
#pragma unroll
    for (int i = 0; i < 4; i++) {
        int idx = (tid & 255) + i * 256;
        int f = idx >> 5, ln = idx & 31;
        bdst[i] = sb + XP_B + ((u32)idx << 4);
        bsrc[i] = ((size_t)(nbx * 16 + (f >> 1)) * 32 + (f & 1)) * 32 + ln;
    }
    u32 aF[2];
#pragma unroll
    for (int mt = 0; mt < 2; mt++)
        aF[mt] = sb + ((wg2 * 2 + mt) * 16 + (lane & 15)) * 80 + ((lane >> 4) * 16);

    auto issue = [&](int kk) {
        const u32 soff = (u32)(kk & 3) * XP_ST;
        if (doA) {
#pragma unroll
            for (int i = 0; i < 4; i++)
                cpa16(adst[i] + soff, asrc[i] + kk * 32);
        } else {
#pragma unroll
            for (int i = 0; i < 4; i++)
                cpa16(bdst[i] + soff, g_wih0p + bsrc[i] + (size_t)kk * 64);
        }
    };

    issue(0); cpa_commit();
    issue(1); cpa_commit();

#pragma unroll 1
    for (int kk = 0; kk < 16; kk += 2) {
        cpa_wait<0>();
        __syncthreads();
        if (kk + 2 < 16) {
            issue(kk + 2); cpa_commit();
            issue(kk + 3); cpa_commit();
        }
#pragma unroll
        for (int half = 0; half < 2; half++) {
            const int s = (kk + half) & 3;
            const uint4* bst = (const uint4*)(smem + (size_t)s * XP_ST + XP_B);
#pragma unroll
            for (int sub = 0; sub < 2; sub++) {
                u32 ah[2][4], al[2][4];
#pragma unroll
                for (int mt = 0; mt < 2; mt++) {
                    ldm4(ah[mt], aF[mt] + (u32)s * XP_ST + sub * 32);
                    ldm4(al[mt], aF[mt] + (u32)s * XP_ST + 10240 + sub * 32);
                }
#pragma unroll
                for (int j = 0; j < 4; j++) {
                    int f = (nq * 4 + j) * 2 + sub;
                    uint4 bp = bst[f * 32 + lane];
                    u32 bh[2] = {bp.x, bp.y}, bl[2] = {bp.z, bp.w};
#pragma unroll
                    for (int mt = 0; mt < 2; mt++) {
                        mma_f16(acc[mt][j], ah[mt], bh);
                        mma_f16(acc[mt][j], al[mt], bh);
                        mma_f16(acc[mt][j], ah[mt], bl);
                    }
                }
            }
        }
    }

#pragma unroll
    for (int mt = 0; mt < 2; mt++) {
        int rl = (wg2 * 2 + mt) * 16 + qr;
        size_t rowbase = ((size_t)mb * 128 + rl) * G4;
#pragma unroll
        for (int j = 0; j < 4; j++) {
            int col = nbx * 128 + (nq * 4 + j) * 8 + qc * 2;
            float bv0 = bih0[col] + bhh0[col];
            float bv1 = bih0[col + 1] + bhh0[col + 1];
            *(float2*)&g_xproj[rowbase + col] =
                make_float2(acc[mt][j][0] + bv0, acc[mt][j][1] + bv1);
            *(float2*)&g_xproj[rowbase + (size_t)8 * G4 + col] =
                make_float2(acc[mt][j][2] + bv0, acc[mt][j][3] + bv1);
        }
    }
}

// ===========================================================================
// Persistent fused-step kernel (round-11 structure, 2-limb weights).
// Grid 128, 768 threads = 24 warps; wg = w&7 -> mtile, job = w>>3:
//   job0: h0(t+1)@Wih1 -> L1 part a; job1: h1(t)@Whh1 -> L1 part b (smem);
//   job2: h0(t+1)@Whh0 -> L0(t+1).
// Product per element: (ah+al)·bh  (weights fp16-rounded; h exact hi+lo).
// 16 MMA/chunk/warp. B prefetched across the grid barrier.
// ===========================================================================
__global__ void __launch_bounds__(768) step_persist(
    const float* __restrict__ bih1, const float* __restrict__ bhh1)
{
    extern __shared__ char smem[];
    const int tid = threadIdx.x, bx = blockIdx.x;
    const int w = tid >> 5, lane = tid & 31, qr = lane >> 2, qc = lane & 3;
    const int wg = w & 7, job = w >> 3;
    const u32 sb = smem_u32(smem);
    const int n0 = bx * 8 + qc * 2;

    // ---- prologue: L0 step 0 (h0 = 0) on this CTA's 8 columns ----
    for (int i = tid; i < 128 * 8; i += 768) {
        int m = i >> 3, u = i & 7;
        int n = bx * 8 + u;
        const float* xr = g_xproj + (size_t)m * G4;
        float iv = xr[n], gv = xr[2048 + n], ov = xr[3072 + n];
        float cn = sigm(iv) * tanhf(gv);
        g_c0[m * HID + n] = cn;
        float h = sigm(ov) * tanhf(cn);
        __half hh = __float2half_rn(h);
        g_h0hi[1][m * HID + n] = hh;
        g_h0lo[1][m * HID + n] = __float2half_rn(h - __half2float(hh));
    }
    grid_barrier(0);

    // biases (L1) in regs (job0 uses them)
    float bs[4][2];
#pragma unroll
    for (int g = 0; g < 4; g++) {
        bs[g][0] = bih1[g * 1024 + n0] + bhh1[g * 1024 + n0];
        bs[g][1] = bih1[g * 1024 + n0 + 1] + bhh1[g * 1024 + n0 + 1];
    }
    // c-state in regs: job0 -> c1 (zeros), job2 -> c0 (from prologue)
    float cr[4] = {0.f, 0.f, 0.f, 0.f};
    if (job == 2) {
#pragma unroll
        for (int rr = 0; rr < 2; rr++) {
            int m = wg * 16 + qr + rr * 8;
            cr[rr * 2 + 0] = g_c0[m * HID + n0];
            cr[rr * 2 + 1] = g_c0[m * HID + n0 + 1];
        }
    }

    // ---- invariant staging coords ----
    const bool doA = (tid < 512);
    u32 adst[4]; u32 arow[4]; int aplane[4]; int aseg[4];
#pragma unroll
    for (int i = 0; i < 4; i++) {
        int idx = (tid & 511) + i * 512;
        aplane[i] = idx >> 9;
        arow[i] = (idx >> 2) & 127;
        aseg[i] = idx & 3;
        adst[i] = sb + aplane[i] * 10240 + arow[i] * 80 + aseg[i] * 16;
    }
    const int btl = tid & 255;
    const int tw = btl >> 5;
    const u32 bdst0 = sb + ST_B + (btl << 4);
    const size_t bsrc0 = (((size_t)((tw >> 1) * 128 + bx)) * 64 + (tw & 1)) * 32 + lane;
    const u32 jobAoff = (job == 1) ? 20480u : 0u;
    const u32 aF = sb + jobAoff + (wg * 16 + (lane & 15)) * 80 + ((lane >> 4) * 16);
    const int bmat = job * 256;

    float* red = (float*)smem;   // 16KB partial buffer (reuses stage 0 A area)

    auto issueB = [&](int kk) {
        const u32 soff = (u32)(kk & 3) * ST_SZ;
        cpa16(bdst0 + soff,        g_wih1p + bsrc0 + (size_t)kk * 64);
        cpa16(bdst0 + soff + 4096, g_whh1p + bsrc0 + (size_t)kk * 64);
        cpa16(bdst0 + soff + 8192, g_whh0p + bsrc0 + (size_t)kk * 64);
    };

    // initial B prefetch (chunks 0,1)
    if (!doA) {
        issueB(0); cpa_commit();
        issueB(1); cpa_commit();
    }

#pragma unroll 1
    for (int t = 0; t < STEPS; t++) {
        const int do_l0 = (t < STEPS - 1);
        const __half* Ap0 = g_h0hi[(t + 1) & 1];
        const __half* Ap1 = g_h0lo[(t + 1) & 1];
        const __half* Ap2 = g_h1hi[t & 1];
        const __half* Ap3 = g_h1lo[t & 1];

        float acc[4][4];
#pragma unroll
        for (int j = 0; j < 4; j++)
#pragma unroll
            for (int k = 0; k < 4; k++) acc[j][k] = 0.f;

        auto issueA = [&](int kk) {
            const u32 soff = (u32)(kk & 3) * ST_SZ;
#pragma unroll
            for (int i = 0; i < 4; i++) {
                const __half* base = (aplane[i] == 0) ? Ap0 :
                                     (aplane[i] == 1) ? Ap1 :
                                     (aplane[i] == 2) ? Ap2 : Ap3;
                cpa16(adst[i] + soff,
                      base + (size_t)arow[i] * HID + kk * 32 + aseg[i] * 8);
            }
        };

        if (doA) {
            issueA(0); cpa_commit();
            issueA(1); cpa_commit();
        }

#pragma unroll 1
        for (int kk = 0; kk < 32; kk += 2) {
            cpa_wait<0>();
            __syncthreads();
            if (kk + 2 < 32) {
                if (doA) issueA(kk + 2); else issueB(kk + 2);
                cpa_commit();
                if (doA) issueA(kk + 3); else issueB(kk + 3);
                cpa_commit();
            }
#pragma unroll
            for (int half = 0; half < 2; half++) {
                const int s = (kk + half) & 3;
                const u32 aBase = aF + (u32)s * ST_SZ;
                const uint4* bst = (const uint4*)(smem + (size_t)s * ST_SZ + ST_B);
#pragma unroll
                for (int sub = 0; sub < 2; sub++) {
                    u32 ah[4], al[4];
                    ldm4(ah, aBase + sub * 32);
                    ldm4(al, aBase + sub * 32 + 10240);
#pragma unroll
                    for (int nt = 0; nt < 4; nt++) {
                        uint4 bp = bst[bmat + (nt * 2 + sub) * 32 + lane];
                        u32 bh[2] = {bp.x, bp.y};
                        mma_f16(acc[nt], ah, bh);
                        mma_f16(acc[nt], al, bh);
                    }
                }
            }
        }
        cpa_wait<0>();
        __syncthreads();

        // prefetch next step's B (weights step-invariant; stages 0,1 free)
        if (!doA && t + 1 < STEPS) {
            issueB(0); cpa_commit();
            issueB(1); cpa_commit();
        }

        // ---- combine: job1 publishes L1 partials ----
        if (job == 1) {
#pragma unroll
            for (int nt = 0; nt < 4; nt++)
#pragma unroll
                for (int r = 0; r < 4; r++)
                    red[(((wg * 4 + nt) * 4 + r) << 5) + lane] = acc[nt][r];
        }
        __syncthreads();

        if (job == 0) {
            // ---- L1(t) epilogue ----
            __half* Hhi = g_h1hi[(t + 1) & 1];
            __half* Hlo = g_h1lo[(t + 1) & 1];
#pragma unroll
            for (int rr = 0; rr < 2; rr++) {
                int m = wg * 16 + qr + rr * 8;
                __half hh[2], hl[2];
#pragma unroll
                for (int e = 0; e < 2; e++) {
                    int ri = rr * 2 + e;
                    float pI = red[(((wg * 4 + 0) * 4 + ri) << 5) + lane];
                    float pF = red[(((wg * 4 + 1) * 4 + ri) << 5) + lane];
                    float pG = red[(((wg * 4 + 2) * 4 + ri) << 5) + lane];
                    float pO = red[(((wg * 4 + 3) * 4 + ri) << 5) + lane];
                    float iv = acc[0][ri] + pI + bs[0][e];
                    float fv = acc[1][ri] + pF + bs[1][e];
                    float gv = acc[2][ri] + pG + bs[2][e];
                    float ov = acc[3][ri] + pO + bs[3][e];
                    float cn = sigm(fv) * cr[ri] + sigm(iv) * tanhf(gv);
                    cr[ri] = cn;
                    float h = sigm(ov) * tanhf(cn);
                    hh[e] = __float2half_rn(h);
                    hl[e] = __float2half_rn(h - __half2float(hh[e]));
                }
                *(__half2*)&Hhi[m * HID + n0] = __halves2half2(hh[0], hh[1]);
                *(__half2*)&Hlo[m * HID + n0] = __halves2half2(hl[0], hl[1]);
            }
        } else if (job == 2 && do_l0) {
            // ---- L0(t+1) epilogue ----
            const float* xp = g_xproj + (size_t)(t + 1) * BATCH * G4;
            __half* Hhi = g_h0hi[t & 1];
            __half* Hlo = g_h0lo[t & 1];
#pragma unroll
            for (int rr = 0; rr < 2; rr++) {
                int m = wg * 16 + qr + rr * 8;
                const float* xr = xp + (size_t)m * G4 + n0;
                float2 xi = *(const float2*)(xr);
                float2 xf = *(const float2*)(xr + 1024);
                float2 xg = *(const float2*)(xr + 2048);
                float2 xo = *(const float2*)(xr + 3072);
                __half hh[2], hl[2];
#pragma unroll
                for (int e = 0; e < 2; e++) {
                    int ri = rr * 2 + e;
                    float iv = acc[0][ri] + (e ? xi.y : xi.x);
                    float fv = acc[1][ri] + (e ? xf.y : xf.x);
                    float gv = acc[2][ri] + (e ? xg.y : xg.x);
                    float ov = acc[3][ri] + (e ? xo.y : xo.x);
                    float cn = sigm(fv) * cr[ri] + sigm(iv) * tanhf(gv);
                    cr[ri] = cn;
                    float h = sigm(ov) * tanhf(cn);
                    hh[e] = __float2half_rn(h);
                    hl[e] = __float2half_rn(h - __half2float(hh[e]));
                }
                *(__half2*)&Hhi[m * HID + n0] = __halves2half2(hh[0], hh[1]);
                *(__half2*)&Hlo[m * HID + n0] = __halves2half2(hl[0], hl[1]);
            }
        }
        grid_barrier(t + 1);
    }
}

// ---------------- classifier (unchanged) ------------------------------------
__global__ void __launch_bounds__(256) classifier_kernel(
    const float* __restrict__ Wcls, const float* __restrict__ bcls,
    const float* __restrict__ dropu, float* __restrict__ out)
{
    int gw = (blockIdx.x * blockDim.x + threadIdx.x) >> 5;
    int lane = threadIdx.x & 31;
    int j = gw >> 5;
    int b0 = (gw & 31) * 4;
    const __half* hi = g_h1hi[0];
    const __half* lo = g_h1lo[0];

    float acc[4] = {0.f, 0.f, 0.f, 0.f};
#pragma unroll
    for (int it = 0; it < 8; ++it) {
        int h = it * 128 + lane * 4;
        float4 wv = *(const float4*)&Wcls[(size_t)j * HID + h];
#pragma unroll
        for (int bi = 0; bi < 4; ++bi) {
            int b = b0 + bi;
            int idx = b * HID + h;
            __half2 a0 = *(const __half2*)&hi[idx];
            __half2 a1 = *(const __half2*)&hi[idx + 2];
            __half2 c0 = *(const __half2*)&lo[idx];
            __half2 c1 = *(const __half2*)&lo[idx + 2];
            float2 f0 = __half22float2(a0), f1 = __half22float2(a1);
            float2 g0 = __half22float2(c0), g1 = __half22float2(c1);
            float x0 = f0.x + g0.x, x1 = f0.y + g0.y;
            float x2 = f1.x + g1.x, x3 = f1.y + g1.y;
            float4 u = *(const float4*)&dropu[(size_t)b * HID + h];
            acc[bi] += (u.x > 0.5f ? x0 : 0.f) * wv.x
                     + (u.y > 0.5f ? x1 : 0.f) * wv.y
                     + (u.z > 0.5f ? x2 : 0.f) * wv.z
                     + (u.w > 0.5f ? x3 : 0.f) * wv.w;
        }
    }
#pragma unroll
    for (int bi = 0; bi < 4; ++bi) {
        float v = acc[bi];
#pragma unroll
        for (int off = 16; off; off >>= 1)
            v += __shfl_xor_sync(0xffffffffu, v, off);
        if (lane == 0)
            out[(size_t)(b0 + bi) * 1000 + j] = 2.0f * v + bcls[j];
    }
}

// ---------------- launch ----------------------------------------------------
extern "C" void kernel_launch(void* const* d_in, const int* in_sizes, int n_in,
                              void* d_out, int out_size)
{
    const float* xs    = (const float*)d_in[0];
    const float* Wih0  = (const float*)d_in[1];
    const float* Whh0  = (const float*)d_in[2];
    const float* bih0  = (const float*)d_in[3];
    const float* bhh0  = (const float*)d_in[4];
    const float* Wih1  = (const float*)d_in[5];
    const float* Whh1  = (const float*)d_in[6];
    const float* bih1  = (const float*)d_in[7];
    const float* bhh1  = (const float*)d_in[8];
    const float* Wcls  = (const float*)d_in[9];
    const float* bcls  = (const float*)d_in[10];
    const float* dropu = (const float*)d_in[11];
    float* out = (float*)d_out;

    cudaFuncSetAttribute(step_persist, cudaFuncAttributeMaxDynamicSharedMemorySize, PS_TOTAL);
    cudaFuncSetAttribute(xproj_kernel, cudaFuncAttributeMaxDynamicSharedMemorySize, XP_TOTAL);

    init_states<<<(BATCH * HID + 255) / 256, 256>>>();
    pack_all<<<(PACK_TOTAL + 255) / 256, 256>>>(Whh0, Wih1, Whh1, Wih0, xs);
    xproj_kernel<<<dim3(32, 64), 512, XP_TOTAL>>>(bih0, bhh0);
    step_persist<<<128, 768, PS_TOTAL>>>(bih1, bhh1);
    classifier_kernel<<<4000, 256>>>(Wcls, bcls, dropu, out);
}

// round 14
// speedup vs baseline: 1.2342x; 1.1176x over previous
#include <cuda_runtime.h>
#include <cuda_fp16.h>

#define BATCH 128
#define DIN   512
#define HID   1024
#define G4    4096
#define STEPS 64
#define TOFF  55   // (128 - 64 - 9)

typedef unsigned int u32;

// ---------------- device scratch (no allocations allowed) -----------------
__device__ float  g_xproj[(size_t)STEPS * BATCH * G4];
__device__ __half g_h0hi[2][BATCH * HID], g_h0lo[2][BATCH * HID];
__device__ __half g_h1hi[2][BATCH * HID], g_h1lo[2][BATCH * HID];
__device__ float  g_c0[BATCH * HID];
__device__ __half g_xshi[(size_t)STEPS * BATCH * DIN];
__device__ __half g_xslo[(size_t)STEPS * BATCH * DIN];
__device__ uint2  g_whh0p[(size_t)512 * 64 * 32];   // hi-only, 8MB
__device__ uint2  g_wih1p[(size_t)512 * 64 * 32];
__device__ uint2  g_whh1p[(size_t)512 * 64 * 32];
__device__ uint4  g_wih0p[(size_t)512 * 32 * 32];   // 3-limb for xproj
__device__ u32    g_bar_count, g_bar_gen;

__device__ __forceinline__ float sigm(float x) { return 1.0f / (1.0f + expf(-x)); }
__device__ __forceinline__ u32 h2u(__half2 h) { return *(u32*)&h; }

__device__ __forceinline__ void mma_f16(float* d, const u32* a, const u32* b) {
    asm volatile("mma.sync.aligned.m16n8k16.row.col.f32.f16.f16.f32 "
        "{%0,%1,%2,%3},{%4,%5,%6,%7},{%8,%9},{%0,%1,%2,%3};"
        : "+f"(d[0]), "+f"(d[1]), "+f"(d[2]), "+f"(d[3])
        : "r"(a[0]), "r"(a[1]), "r"(a[2]), "r"(a[3]), "r"(b[0]), "r"(b[1]));
}
__device__ __forceinline__ u32 smem_u32(const void* p) {
    u32 a;
    asm("{ .reg .u64 t; cvta.to.shared.u64 t, %1; cvt.u32.u64 %0, t; }" : "=r"(a) : "l"(p));
    return a;
}
__device__ __forceinline__ void cpa16(u32 dst, const void* src) {
    asm volatile("cp.async.cg.shared.global [%0], [%1], 16;"
                 :: "r"(dst), "l"(__cvta_generic_to_global(src)) : "memory");
}
__device__ __forceinline__ void cpa8(u32 dst, const void* src) {
    asm volatile("cp.async.ca.shared.global [%0], [%1], 8;"
                 :: "r"(dst), "l"(__cvta_generic_to_global(src)) : "memory");
}
__device__ __forceinline__ void cpa_commit() {
    asm volatile("cp.async.commit_group;" ::: "memory");
}
template<int N> __device__ __forceinline__ void cpa_wait() {
    asm volatile("cp.async.wait_group %0;" :: "n"(N) : "memory");
}
__device__ __forceinline__ void ldm4(u32* r, u32 addr) {
    asm volatile("ldmatrix.sync.aligned.m8n8.x4.shared.b16 {%0,%1,%2,%3}, [%4];"
        : "=r"(r[0]), "=r"(r[1]), "=r"(r[2]), "=r"(r[3]) : "r"(addr));
}

// step-kernel smem: 4 stages of 47104 B (A 4 planes x 10240 | B 3 x 2048)
#define ST_SZ    47104
#define ST_B     40960
#define PS_TOTAL (4 * ST_SZ)

// xproj smem: 4 stages of 36864 B (Ahi 10240 | Alo 10240 | B 16384)
#define XP_ST    36864
#define XP_B     20480
#define XP_TOTAL (4 * XP_ST)

// ---------------- grid-wide software barrier (128 CTAs) --------------------
__device__ __forceinline__ void grid_barrier(int gen) {
    __syncthreads();
    if (threadIdx.x == 0) {
        __threadfence();
        u32 prev = atomicAdd(&g_bar_count, 1u);
        if (prev == (u32)(gen * 128 + 127)) {
            atomicExch(&g_bar_gen, (u32)(gen + 1));
        } else {
            u32 g;
            do {
                __nanosleep(64);
                asm volatile("ld.acquire.gpu.u32 %0, [%1];"
                             : "=r"(g) : "l"((const u32*)&g_bar_gen));
            } while (g <= (u32)gen);
        }
    }
    __syncthreads();
}

// ---------------- init states ----------------------------------------------
__global__ void init_states() {
    int i = blockIdx.x * blockDim.x + threadIdx.x;
    if (i == 0) { g_bar_count = 0u; g_bar_gen = 0u; }
    if (i < BATCH * HID) {
        __half z = __float2half(0.f);
        g_h0hi[0][i] = z; g_h0lo[0][i] = z; g_h0hi[1][i] = z; g_h0lo[1][i] = z;
        g_h1hi[0][i] = z; g_h1lo[0][i] = z; g_h1hi[1][i] = z; g_h1lo[1][i] = z;
        g_c0[i] = 0.f;
    }
}

// ---------------- packers (single launch) ----------------------------------
// hi-only packer for recurrent weights (uint2)
__device__ __forceinline__ void pack_hi(
    const float* __restrict__ W, uint2* __restrict__ dst, int idx)
{
    int lane = idx & 31;
    int rest = idx >> 5;
    int kt = rest & 63, nt = rest >> 6;
    int n = nt * 8 + (lane >> 2);
    int k0 = kt * 16 + (lane & 3) * 2;
    const float* wr = W + (size_t)n * HID + k0;
    uint2 v;
    v.x = h2u(__halves2half2(__float2half_rn(wr[0]), __float2half_rn(wr[1])));
    v.y = h2u(__halves2half2(__float2half_rn(wr[8]), __float2half_rn(wr[9])));
    dst[idx] = v;
}
// 3-limb packer for xproj weights (uint4)
__device__ __forceinline__ void pack_one32(
    const float* __restrict__ W, uint4* __restrict__ dst, int idx)
{
    int lane = idx & 31;
    int rest = idx >> 5;
    int kt = rest & 31, nt = rest >> 5;
    int n = nt * 8 + (lane >> 2);
    int k0 = kt * 16 + (lane & 3) * 2;
    const float* wr = W + (size_t)n * DIN + k0;
    float w00 = wr[0], w01 = wr[1], w10 = wr[8], w11 = wr[9];
    __half h00 = __float2half_rn(w00), h01 = __float2half_rn(w01);
    __half h10 = __float2half_rn(w10), h11 = __float2half_rn(w11);
    uint4 v;
    v.x = h2u(__halves2half2(h00, h01));
    v.y = h2u(__halves2half2(h10, h11));
    v.z = h2u(__halves2half2(__float2half_rn(w00 - __half2float(h00)),
                             __float2half_rn(w01 - __half2float(h01))));
    v.w = h2u(__halves2half2(__float2half_rn(w10 - __half2float(h10)),
                             __float2half_rn(w11 - __half2float(h11))));
    dst[idx] = v;
}
__device__ __forceinline__ void pack_xs_one(const float* __restrict__ xs, int idx) {
    int k = idx & 511;
    int b = (idx >> 9) & 127;
    int t = idx >> 16;
    float x = xs[((size_t)(b * 128 + TOFF + t)) * DIN + k];
    __half h = __float2half_rn(x);
    g_xshi[idx] = h;
    g_xslo[idx] = __float2half_rn(x - __half2float(h));
}
#define PACK_N64 (512 * 64 * 32)
#define PACK_N32 (512 * 32 * 32)
#define PACK_XS  (STEPS * BATCH * DIN)
#define PACK_TOTAL (3 * PACK_N64 + PACK_N32 + PACK_XS)
__global__ void pack_all(const float* __restrict__ Whh0, const float* __restrict__ Wih1,
                         const float* __restrict__ Whh1, const float* __restrict__ Wih0,
                         const float* __restrict__ xs) {
    int idx = blockIdx.x * 256 + threadIdx.x;
    if (idx < PACK_N64)                          pack_hi(Whh0, g_whh0p, idx);
    else if (idx < 2 * PACK_N64)                 pack_hi(Wih1, g_wih1p, idx - PACK_N64);
    else if (idx < 3 * PACK_N64)                 pack_hi(Whh1, g_whh1p, idx - 2 * PACK_N64);
    else if (idx < 3 * PACK_N64 + PACK_N32)      pack_one32(Wih0, g_wih0p, idx - 3 * PACK_N64);
    else                                         pack_xs_one(xs, idx - 3 * PACK_N64 - PACK_N32);
}

// ===========================================================================
// xproj v3 (round-11 validated, 3-limb, unchanged)
// ===========================================================================
__global__ void __launch_bounds__(512) xproj_kernel(
    const float* __restrict__ bih0, const float* __restrict__ bhh0)
{
    extern __shared__ char smem[];
    const int tid = threadIdx.x;
    const int nbx = blockIdx.x;
    const int mb  = blockIdx.y;
    const int w = tid >> 5, lane = tid & 31, qr = lane >> 2, qc = lane & 3;
    const int wg2 = w & 3, nq = w >> 2;
    const u32 sb = smem_u32(smem);

    float acc[2][4][4];
#pragma unroll
    for (int i = 0; i < 2; i++)
#pragma unroll
        for (int j = 0; j < 4; j++)
#pragma unroll
            for (int k = 0; k < 4; k++) acc[i][j][k] = 0.f;

    const bool doA = (tid < 256);
    u32 adst[4]; const __half* asrc[4];
#pragma unroll
    for (int i = 0; i < 4; i++) {
        int idx = (tid & 255) + i * 256;
        int plane = idx >> 9, row = (idx >> 2) & 127, seg = idx & 3;
        adst[i] = sb + plane * 10240 + row * 80 + seg * 16;
        const __half* base = plane ? g_xslo : g_xshi;
        asrc[i] = base + (size_t)(mb * 128 + row) * DIN + seg * 8;
    }
    u32 bdst[4]; size_t bsrc[4];
#pragma unroll
    for (int i = 0; i < 4; i++) {
        int idx = (tid & 255) + i * 256;
        int f = idx >> 5, ln = idx & 31;
        bdst[i] = sb + XP_B + ((u32)idx << 4);
        bsrc[i] = ((size_t)(nbx * 16 + (f >> 1)) * 32 + (f & 1)) * 32 + ln;
    }
    u32 aF[2];
#pragma unroll
    for (int mt = 0; mt < 2; mt++)
        aF[mt] = sb + ((wg2 * 2 + mt) * 16 + (lane & 15)) * 80 + ((lane >> 4) * 16);

    auto issue = [&](int kk) {
        const u32 soff = (u32)(kk & 3) * XP_ST;
        if (doA) {
#pragma unroll
            for (int i = 0; i < 4; i++)
                cpa16(adst[i] + soff, asrc[i] + kk * 32);
        } else {
#pragma unroll
            for (int i = 0; i < 4; i++)
                cpa16(bdst[i] + soff, g_wih0p + bsrc[i] + (size_t)kk * 64);
        }
    };

    issue(0); cpa_commit();
    issue(1); cpa_commit();

#pragma unroll 1
    for (int kk = 0; kk < 16; kk += 2) {
        cpa_wait<0>();
        __syncthreads();
        if (kk + 2 < 16) {
            issue(kk + 2); cpa_commit();
            issue(kk + 3); cpa_commit();
        }
#pragma unroll
        for (int half = 0; half < 2; half++) {
            const int s = (kk + half) & 3;
            const uint4* bst = (const uint4*)(smem + (size_t)s * XP_ST + XP_B);
#pragma unroll
            for (int sub = 0; sub < 2; sub++) {
                u32 ah[2][4], al[2][4];
#pragma unroll
                for (int mt = 0; mt < 2; mt++) {
                    ldm4(ah[mt], aF[mt] + (u32)s * XP_ST + sub * 32);
                    ldm4(al[mt], aF[mt] + (u32)s * XP_ST + 10240 + sub * 32);
                }
#pragma unroll
                for (int j = 0; j < 4; j++) {
                    int f = (nq * 4 + j) * 2 + sub;
                    uint4 bp = bst[f * 32 + lane];
                    u32 bh[2] = {bp.x, bp.y}, bl[2] = {bp.z, bp.w};
#pragma unroll
                    for (int mt = 0; mt < 2; mt++) {
                        mma_f16(acc[mt][j], ah[mt], bh);
                        mma_f16(acc[mt][j], al[mt], bh);
                        mma_f16(acc[mt][j], ah[mt], bl);
                    }
                }
            }
        }
    }

#pragma unroll
    for (int mt = 0; mt < 2; mt++) {
        int rl = (wg2 * 2 + mt) * 16 + qr;
        size_t rowbase = ((size_t)mb * 128 + rl) * G4;
#pragma unroll
        for (int j = 0; j < 4; j++) {
            int col = nbx * 128 + (nq * 4 + j) * 8 + qc * 2;
            float bv0 = bih0[col] + bhh0[col];
            float bv1 = bih0[col + 1] + bhh0[col + 1];
            *(float2*)&g_xproj[rowbase + col] =
                make_float2(acc[mt][j][0] + bv0, acc[mt][j][1] + bv1);
            *(float2*)&g_xproj[rowbase + (size_t)8 * G4 + col] =
                make_float2(acc[mt][j][2] + bv0, acc[mt][j][3] + bv1);
        }
    }
}

// ===========================================================================
// Persistent fused-step kernel (round-13 structure, uint2 hi-only weights).
// Grid 128, 768 threads = 24 warps; wg = w&7 -> mtile, job = w>>3:
//   job0: h0(t+1)@Wih1 -> L1 part a; job1: h1(t)@Whh1 -> L1 part b (smem);
//   job2: h0(t+1)@Whh0 -> L0(t+1).
// Product: (ah+al)·bh. B reads are LDS.64; B staging is cp.async 8B.
// ===========================================================================
__global__ void __launch_bounds__(768) step_persist(
    const float* __restrict__ bih1, const float* __restrict__ bhh1)
{
    extern __shared__ char smem[];
    const int tid = threadIdx.x, bx = blockIdx.x;
    const int w = tid >> 5, lane = tid & 31, qr = lane >> 2, qc = lane & 3;
    const int wg = w & 7, job = w >> 3;
    const u32 sb = smem_u32(smem);
    const int n0 = bx * 8 + qc * 2;

    // ---- prologue: L0 step 0 (h0 = 0) on this CTA's 8 columns ----
    for (int i = tid; i < 128 * 8; i += 768) {
        int m = i >> 3, u = i & 7;
        int n = bx * 8 + u;
        const float* xr = g_xproj + (size_t)m * G4;
        float iv = xr[n], gv = xr[2048 + n], ov = xr[3072 + n];
        float cn = sigm(iv) * tanhf(gv);
        g_c0[m * HID + n] = cn;
        float h = sigm(ov) * tanhf(cn);
        __half hh = __float2half_rn(h);
        g_h0hi[1][m * HID + n] = hh;
        g_h0lo[1][m * HID + n] = __float2half_rn(h - __half2float(hh));
    }
    grid_barrier(0);

    // biases (L1) in regs (job0 uses them)
    float bs[4][2];
#pragma unroll
    for (int g = 0; g < 4; g++) {
        bs[g][0] = bih1[g * 1024 + n0] + bhh1[g * 1024 + n0];
        bs[g][1] = bih1[g * 1024 + n0 + 1] + bhh1[g * 1024 + n0 + 1];
    }
    // c-state in regs: job0 -> c1 (zeros), job2 -> c0 (from prologue)
    float cr[4] = {0.f, 0.f, 0.f, 0.f};
    if (job == 2) {
#pragma unroll
        for (int rr = 0; rr < 2; rr++) {
            int m = wg * 16 + qr + rr * 8;
            cr[rr * 2 + 0] = g_c0[m * HID + n0];
            cr[rr * 2 + 1] = g_c0[m * HID + n0 + 1];
        }
    }

    // ---- invariant staging coords ----
    const bool doA = (tid < 512);
    u32 adst[4]; u32 arow[4]; int aplane[4]; int aseg[4];
#pragma unroll
    for (int i = 0; i < 4; i++) {
        int idx = (tid & 511) + i * 512;
        aplane[i] = idx >> 9;
        arow[i] = (idx >> 2) & 127;
        aseg[i] = idx & 3;
        adst[i] = sb + aplane[i] * 10240 + arow[i] * 80 + aseg[i] * 16;
    }
    const int btl = tid & 255;
    const int tw = btl >> 5;
    const u32 bdst0 = sb + ST_B + (btl << 3);
    const size_t bsrc0 = (((size_t)((tw >> 1) * 128 + bx)) * 64 + (tw & 1)) * 32 + lane;
    const u32 jobAoff = (job == 1) ? 20480u : 0u;
    const u32 aF = sb + jobAoff + (wg * 16 + (lane & 15)) * 80 + ((lane >> 4) * 16);
    const int bmat = job * 256;

    float* red = (float*)smem;   // 16KB partial buffer (reuses stage 0 A area)

    auto issueB = [&](int kk) {
        const u32 soff = (u32)(kk & 3) * ST_SZ;
        cpa8(bdst0 + soff,        g_wih1p + bsrc0 + (size_t)kk * 64);
        cpa8(bdst0 + soff + 2048, g_whh1p + bsrc0 + (size_t)kk * 64);
        cpa8(bdst0 + soff + 4096, g_whh0p + bsrc0 + (size_t)kk * 64);
    };

    // initial B prefetch (chunks 0,1)
    if (!doA) {
        issueB(0); cpa_commit();
        issueB(1); cpa_commit();
    }

#pragma unroll 1
    for (int t = 0; t < STEPS; t++) {
        const int do_l0 = (t < STEPS - 1);
        const __half* Ap0 = g_h0hi[(t + 1) & 1];
        const __half* Ap1 = g_h0lo[(t + 1) & 1];
        const __half* Ap2 = g_h1hi[t & 1];
        const __half* Ap3 = g_h1lo[t & 1];

        float acc[4][4];
#pragma unroll
        for (int j = 0; j < 4; j++)
#pragma unroll
            for (int k = 0; k < 4; k++) acc[j][k] = 0.f;

        auto issueA = [&](int kk) {
            const u32 soff = (u32)(kk & 3) * ST_SZ;
#pragma unroll
            for (int i = 0; i < 4; i++) {
                const __half* base = (aplane[i] == 0) ? Ap0 :
                                     (aplane[i] == 1) ? Ap1 :
                                     (aplane[i] == 2) ? Ap2 : Ap3;
                cpa16(adst[i] + soff,
                      base + (size_t)arow[i] * HID + kk * 32 + aseg[i] * 8);
            }
        };

        if (doA) {
            issueA(0); cpa_commit();
            issueA(1); cpa_commit();
        }

#pragma unroll 1
        for (int kk = 0; kk < 32; kk += 2) {
            cpa_wait<0>();
            __syncthreads();
            if (kk + 2 < 32) {
                if (doA) issueA(kk + 2); else issueB(kk + 2);
                cpa_commit();
                if (doA) issueA(kk + 3); else issueB(kk + 3);
                cpa_commit();
            }
#pragma unroll
            for (int half = 0; half < 2; half++) {
                const int s = (kk + half) & 3;
                const u32 aBase = aF + (u32)s * ST_SZ;
                const uint2* bst = (const uint2*)(smem + (size_t)s * ST_SZ + ST_B);
#pragma unroll
                for (int sub = 0; sub < 2; sub++) {
                    u32 ah[4], al[4];
                    ldm4(ah, aBase + sub * 32);
                    ldm4(al, aBase + sub * 32 + 10240);
#pragma unroll
                    for (int nt = 0; nt < 4; nt++) {
                        uint2 bp = bst[bmat + (nt * 2 + sub) * 32 + lane];
                        u32 bh[2] = {bp.x, bp.y};
                        mma_f16(acc[nt], ah, bh);
                        mma_f16(acc[nt], al, bh);
                    }
                }
            }
        }
        cpa_wait<0>();
        __syncthreads();

        // prefetch next step's B (weights step-invariant; stages 0,1 free)
        if (!doA && t + 1 < STEPS) {
            issueB(0); cpa_commit();
            issueB(1); cpa_commit();
        }

        // ---- combine: job1 publishes L1 partials ----
        if (job == 1) {
#pragma unroll
            for (int nt = 0; nt < 4; nt++)
#pragma unroll
                for (int r = 0; r < 4; r++)
                    red[(((wg * 4 + nt) * 4 + r) << 5) + lane] = acc[nt][r];
        }
        __syncthreads();

        if (job == 0) {
            // ---- L1(t) epilogue ----
            __half* Hhi = g_h1hi[(t + 1) & 1];
            __half* Hlo = g_h1lo[(t + 1) & 1];
#pragma unroll
            for (int rr = 0; rr < 2; rr++) {
                int m = wg * 16 + qr + rr * 8;
                __half hh[2], hl[2];
#pragma unroll
                for (int e = 0; e < 2; e++) {
                    int ri = rr * 2 + e;
                    float pI = red[(((wg * 4 + 0) * 4 + ri) << 5) + lane];
                    float pF = red[(((wg * 4 + 1) * 4 + ri) << 5) + lane];
                    float pG = red[(((wg * 4 + 2) * 4 + ri) << 5) + lane];
                    float pO = red[(((wg * 4 + 3) * 4 + ri) << 5) + lane];
                    float iv = acc[0][ri] + pI + bs[0][e];
                    float fv = acc[1][ri] + pF + bs[1][e];
                    float gv = acc[2][ri] + pG + bs[2][e];
                    float ov = acc[3][ri] + pO + bs[3][e];
                    float cn = sigm(fv) * cr[ri] + sigm(iv) * tanhf(gv);
                    cr[ri] = cn;
                    float h = sigm(ov) * tanhf(cn);
                    hh[e] = __float2half_rn(h);
                    hl[e] = __float2half_rn(h - __half2float(hh[e]));
                }
                *(__half2*)&Hhi[m * HID + n0] = __halves2half2(hh[0], hh[1]);
                *(__half2*)&Hlo[m * HID + n0] = __halves2half2(hl[0], hl[1]);
            }
        } else if (job == 2 && do_l0) {
            // ---- L0(t+1) epilogue ----
            const float* xp = g_xproj + (size_t)(t + 1) * BATCH * G4;
            __half* Hhi = g_h0hi[t & 1];
            __half* Hlo = g_h0lo[t & 1];
#pragma unroll
            for (int rr = 0; rr < 2; rr++) {
                int m = wg * 16 + qr + rr * 8;
                const float* xr = xp + (size_t)m * G4 + n0;
                float2 xi = *(const float2*)(xr);
                float2 xf = *(const float2*)(xr + 1024);
                float2 xg = *(const float2*)(xr + 2048);
                float2 xo = *(const float2*)(xr + 3072);
                __half hh[2], hl[2];
#pragma unroll
                for (int e = 0; e < 2; e++) {
                    int ri = rr * 2 + e;
                    float iv = acc[0][ri] + (e ? xi.y : xi.x);
                    float fv = acc[1][ri] + (e ? xf.y : xf.x);
                    float gv = acc[2][ri] + (e ? xg.y : xg.x);
                    float ov = acc[3][ri] + (e ? xo.y : xo.x);
                    float cn = sigm(fv) * cr[ri] + sigm(iv) * tanhf(gv);
                    cr[ri] = cn;
                    float h = sigm(ov) * tanhf(cn);
                    hh[e] = __float2half_rn(h);
                    hl[e] = __float2half_rn(h - __half2float(hh[e]));
                }
                *(__half2*)&Hhi[m * HID + n0] = __halves2half2(hh[0], hh[1]);
                *(__half2*)&Hlo[m * HID + n0] = __halves2half2(hl[0], hl[1]);
            }
        }
        grid_barrier(t + 1);
    }
}

// ---------------- classifier (unchanged) ------------------------------------
__global__ void __launch_bounds__(256) classifier_kernel(
    const float* __restrict__ Wcls, const float* __restrict__ bcls,
    const float* __restrict__ dropu, float* __restrict__ out)
{
    int gw = (blockIdx.x * blockDim.x + threadIdx.x) >> 5;
    int lane = threadIdx.x & 31;
    int j = gw >> 5;
    int b0 = (gw & 31) * 4;
    const __half* hi = g_h1hi[0];
    const __half* lo = g_h1lo[0];

    float acc[4] = {0.f, 0.f, 0.f, 0.f};
#pragma unroll
    for (int it = 0; it < 8; ++it) {
        int h = it * 128 + lane * 4;
        float4 wv = *(const float4*)&Wcls[(size_t)j * HID + h];
#pragma unroll
        for (int bi = 0; bi < 4; ++bi) {
            int b = b0 + bi;
            int idx = b * HID + h;
            __half2 a0 = *(const __half2*)&hi[idx];
            __half2 a1 = *(const __half2*)&hi[idx + 2];
            __half2 c0 = *(const __half2*)&lo[idx];
            __half2 c1 = *(const __half2*)&lo[idx + 2];
            float2 f0 = __half22float2(a0), f1 = __half22float2(a1);
            float2 g0 = __half22float2(c0), g1 = __half22float2(c1);
            float x0 = f0.x + g0.x, x1 = f0.y + g0.y;
            float x2 = f1.x + g1.x, x3 = f1.y + g1.y;
            float4 u = *(const float4*)&dropu[(size_t)b * HID + h];
            acc[bi] += (u.x > 0.5f ? x0 : 0.f) * wv.x
                     + (u.y > 0.5f ? x1 : 0.f) * wv.y
                     + (u.z > 0.5f ? x2 : 0.f) * wv.z
                     + (u.w > 0.5f ? x3 : 0.f) * wv.w;
        }
    }
#pragma unroll
    for (int bi = 0; bi < 4; ++bi) {
        float v = acc[bi];
#pragma unroll
        for (int off = 16; off; off >>= 1)
            v += __shfl_xor_sync(0xffffffffu, v, off);
        if (lane == 0)
            out[(size_t)(b0 + bi) * 1000 + j] = 2.0f * v + bcls[j];
    }
}

// ---------------- launch ----------------------------------------------------
extern "C" void kernel_launch(void* const* d_in, const int* in_sizes, int n_in,
                              void* d_out, int out_size)
{
    const float* xs    = (const float*)d_in[0];
    const float* Wih0  = (const float*)d_in[1];
    const float* Whh0  = (const float*)d_in[2];
    const float* bih0  = (const float*)d_in[3];
    const float* bhh0  = (const float*)d_in[4];
    const float* Wih1  = (const float*)d_in[5];
    const float* Whh1  = (const float*)d_in[6];
    const float* bih1  = (const float*)d_in[7];
    const float* bhh1  = (const float*)d_in[8];
    const float* Wcls  = (const float*)d_in[9];
    const float* bcls  = (const float*)d_in[10];
    const float* dropu = (const float*)d_in[11];
    float* out = (float*)d_out;

    cudaFuncSetAttribute(step_persist, cudaFuncAttributeMaxDynamicSharedMemorySize, PS_TOTAL);
    cudaFuncSetAttribute(xproj_kernel, cudaFuncAttributeMaxDynamicSharedMemorySize, XP_TOTAL);

    init_states<<<(BATCH * HID + 255) / 256, 256>>>();
    pack_all<<<(PACK_TOTAL + 255) / 256, 256>>>(Whh0, Wih1, Whh1, Wih0, xs);
    xproj_kernel<<<dim3(32, 64), 512, XP_TOTAL>>>(bih0, bhh0);
    step_persist<<<128, 768, PS_TOTAL>>>(bih1, bhh1);
    classifier_kernel<<<4000, 256>>>(Wcls, bcls, dropu, out);
}

// round 15
// speedup vs baseline: 1.6519x; 1.3384x over previous
#include <cuda_runtime.h>
#include <cuda_fp16.h>

#define BATCH 128
#define DIN   512
#define HID   1024
#define G4    4096
#define STEPS 64
#define TOFF  55   // (128 - 64 - 9)

typedef unsigned int u32;

// ---------------- device scratch (no allocations allowed) -----------------
__device__ float  g_xproj[(size_t)STEPS * BATCH * G4];
__device__ __half g_h0[2][BATCH * HID];      // fp16-only hidden states
__device__ __half g_h1[2][BATCH * HID];
__device__ float  g_c0[BATCH * HID];
__device__ __half g_xshi[(size_t)STEPS * BATCH * DIN];
__device__ __half g_xslo[(size_t)STEPS * BATCH * DIN];
__device__ uint2  g_whh0p[(size_t)512 * 64 * 32];   // hi-only weights
__device__ uint2  g_wih1p[(size_t)512 * 64 * 32];
__device__ uint2  g_whh1p[(size_t)512 * 64 * 32];
__device__ uint4  g_wih0p[(size_t)512 * 32 * 32];   // 3-limb for xproj
__device__ u32    g_bar_count, g_bar_gen;

__device__ __forceinline__ float sigm(float x) { return 1.0f / (1.0f + expf(-x)); }
__device__ __forceinline__ u32 h2u(__half2 h) { return *(u32*)&h; }

__device__ __forceinline__ void mma_f16(float* d, const u32* a, const u32* b) {
    asm volatile("mma.sync.aligned.m16n8k16.row.col.f32.f16.f16.f32 "
        "{%0,%1,%2,%3},{%4,%5,%6,%7},{%8,%9},{%0,%1,%2,%3};"
        : "+f"(d[0]), "+f"(d[1]), "+f"(d[2]), "+f"(d[3])
        : "r"(a[0]), "r"(a[1]), "r"(a[2]), "r"(a[3]), "r"(b[0]), "r"(b[1]));
}
__device__ __forceinline__ u32 smem_u32(const void* p) {
    u32 a;
    asm("{ .reg .u64 t; cvta.to.shared.u64 t, %1; cvt.u32.u64 %0, t; }" : "=r"(a) : "l"(p));
    return a;
}
__device__ __forceinline__ void cpa16(u32 dst, const void* src) {
    asm volatile("cp.async.cg.shared.global [%0], [%1], 16;"
                 :: "r"(dst), "l"(__cvta_generic_to_global(src)) : "memory");
}
__device__ __forceinline__ void cpa8(u32 dst, const void* src) {
    asm volatile("cp.async.ca.shared.global [%0], [%1], 8;"
                 :: "r"(dst), "l"(__cvta_generic_to_global(src)) : "memory");
}
__device__ __forceinline__ void cpa_commit() {
    asm volatile("cp.async.commit_group;" ::: "memory");
}
template<int N> __device__ __forceinline__ void cpa_wait() {
    asm volatile("cp.async.wait_group %0;" :: "n"(N) : "memory");
}
__device__ __forceinline__ void ldm4(u32* r, u32 addr) {
    asm volatile("ldmatrix.sync.aligned.m8n8.x4.shared.b16 {%0,%1,%2,%3}, [%4];"
        : "=r"(r[0]), "=r"(r[1]), "=r"(r[2]), "=r"(r[3]) : "r"(addr));
}

// step-kernel smem: 4 stages of 26624 B (A 2 planes x 10240 | B 3 x 2048)
#define ST_SZ    26624
#define ST_B     20480
#define PS_TOTAL (4 * ST_SZ)

// xproj smem: 4 stages of 36864 B (Ahi 10240 | Alo 10240 | B 16384)
#define XP_ST    36864
#define XP_B     20480
#define XP_TOTAL (4 * XP_ST)

// ---------------- grid-wide software barrier (128 CTAs) --------------------
__device__ __forceinline__ void grid_barrier(int gen) {
    __syncthreads();
    if (threadIdx.x == 0) {
        __threadfence();
        u32 prev = atomicAdd(&g_bar_count, 1u);
        if (prev == (u32)(gen * 128 + 127)) {
            atomicExch(&g_bar_gen, (u32)(gen + 1));
        } else {
            u32 g;
            do {
                __nanosleep(64);
                asm volatile("ld.acquire.gpu.u32 %0, [%1];"
                             : "=r"(g) : "l"((const u32*)&g_bar_gen));
            } while (g <= (u32)gen);
        }
    }
    __syncthreads();
}

// ---------------- init states ----------------------------------------------
__global__ void init_states() {
    int i = blockIdx.x * blockDim.x + threadIdx.x;
    if (i == 0) { g_bar_count = 0u; g_bar_gen = 0u; }
    if (i < BATCH * HID) {
        __half z = __float2half(0.f);
        g_h0[0][i] = z; g_h0[1][i] = z;
        g_h1[0][i] = z; g_h1[1][i] = z;
        g_c0[i] = 0.f;
    }
}

// ---------------- packers (single launch) ----------------------------------
__device__ __forceinline__ void pack_hi(
    const float* __restrict__ W, uint2* __restrict__ dst, int idx)
{
    int lane = idx & 31;
    int rest = idx >> 5;
    int kt = rest & 63, nt = rest >> 6;
    int n = nt * 8 + (lane >> 2);
    int k0 = kt * 16 + (lane & 3) * 2;
    const float* wr = W + (size_t)n * HID + k0;
    uint2 v;
    v.x = h2u(__halves2half2(__float2half_rn(wr[0]), __float2half_rn(wr[1])));
    v.y = h2u(__halves2half2(__float2half_rn(wr[8]), __float2half_rn(wr[9])));
    dst[idx] = v;
}
__device__ __forceinline__ void pack_one32(
    const float* __restrict__ W, uint4* __restrict__ dst, int idx)
{
    int lane = idx & 31;
    int rest = idx >> 5;
    int kt = rest & 31, nt = rest >> 5;
    int n = nt * 8 + (lane >> 2);
    int k0 = kt * 16 + (lane & 3) * 2;
    const float* wr = W + (size_t)n * DIN + k0;
    float w00 = wr[0], w01 = wr[1], w10 = wr[8], w11 = wr[9];
    __half h00 = __float2half_rn(w00), h01 = __float2half_rn(w01);
    __half h10 = __float2half_rn(w10), h11 = __float2half_rn(w11);
    uint4 v;
    v.x = h2u(__halves2half2(h00, h01));
    v.y = h2u(__halves2half2(h10, h11));
    v.z = h2u(__halves2half2(__float2half_rn(w00 - __half2float(h00)),
                             __float2half_rn(w01 - __half2float(h01))));
    v.w = h2u(__halves2half2(__float2half_rn(w10 - __half2float(h10)),
                             __float2half_rn(w11 - __half2float(h11))));
    dst[idx] = v;
}
__device__ __forceinline__ void pack_xs_one(const float* __restrict__ xs, int idx) {
    int k = idx & 511;
    int b = (idx >> 9) & 127;
    int t = idx >> 16;
    float x = xs[((size_t)(b * 128 + TOFF + t)) * DIN + k];
    __half h = __float2half_rn(x);
    g_xshi[idx] = h;
    g_xslo[idx] = __float2half_rn(x - __half2float(h));
}
#define PACK_N64 (512 * 64 * 32)
#define PACK_N32 (512 * 32 * 32)
#define PACK_XS  (STEPS * BATCH * DIN)
#define PACK_TOTAL (3 * PACK_N64 + PACK_N32 + PACK_XS)
__global__ void pack_all(const float* __restrict__ Whh0, const float* __restrict__ Wih1,
                         const float* __restrict__ Whh1, const float* __restrict__ Wih0,
                         const float* __restrict__ xs) {
    int idx = blockIdx.x * 256 + threadIdx.x;
    if (idx < PACK_N64)                          pack_hi(Whh0, g_whh0p, idx);
    else if (idx < 2 * PACK_N64)                 pack_hi(Wih1, g_wih1p, idx - PACK_N64);
    else if (idx < 3 * PACK_N64)                 pack_hi(Whh1, g_whh1p, idx - 2 * PACK_N64);
    else if (idx < 3 * PACK_N64 + PACK_N32)      pack_one32(Wih0, g_wih0p, idx - 3 * PACK_N64);
    else                                         pack_xs_one(xs, idx - 3 * PACK_N64 - PACK_N32);
}

// ===========================================================================
// xproj v3 (round-11 validated, 3-limb, unchanged)
// ===========================================================================
__global__ void __launch_bounds__(512) xproj_kernel(
    const float* __restrict__ bih0, const float* __restrict__ bhh0)
{
    extern __shared__ char smem[];
    const int tid = threadIdx.x;
    const int nbx = blockIdx.x;
    const int mb  = blockIdx.y;
    const int w = tid >> 5, lane = tid & 31, qr = lane >> 2, qc = lane & 3;
    const int wg2 = w & 3, nq = w >> 2;
    const u32 sb = smem_u32(smem);

    float acc[2][4][4];
#pragma unroll
    for (int i = 0; i < 2; i++)
#pragma unroll
        for (int j = 0; j < 4; j++)
#pragma unroll
            for (int k = 0; k < 4; k++) acc[i][j][k] = 0.f;

    const bool doA = (tid < 256);
    u32 adst[4]; const __half* asrc[4];
#pragma unroll
    for (int i = 0; i < 4; i++) {
        int idx = (tid & 255) + i * 256;
        int plane = idx >> 9, row = (idx >> 2) & 127, seg = idx & 3;
        adst[i] = sb + plane * 10240 + row * 80 + seg * 16;
        const __half* base = plane ? g_xslo : g_xshi;
        asrc[i] = base + (size_t)(mb * 128 + row) * DIN + seg * 8;
    }
    u32 bdst[4]; size_t bsrc[4];
#pragma unroll
    for (int i = 0; i < 4; i++) {
        int idx = (tid & 255) + i * 256;
        int f = idx >> 5, ln = idx & 31;
        bdst[i] = sb + XP_B + ((u32)idx << 4);
        bsrc[i] = ((size_t)(nbx * 16 + (f >> 1)) * 32 + (f & 1)) * 32 + ln;
    }
    u32 aF[2];
#pragma unroll
    for (int mt = 0; mt < 2; mt++)
        aF[mt] = sb + ((wg2 * 2 + mt) * 16 + (lane & 15)) * 80 + ((lane >> 4) * 16);

    auto issue = [&](int kk) {
        const u32 soff = (u32)(kk & 3) * XP_ST;
        if (doA) {
#pragma unroll
            for (int i = 0; i < 4; i++)
                cpa16(adst[i] + soff, asrc[i] + kk * 32);
        } else {
#pragma unroll
            for (int i = 0; i < 4; i++)
                cpa16(bdst[i] + soff, g_wih0p + bsrc[i] + (size_t)kk * 64);
        }
    };

    issue(0); cpa_commit();
    issue(1); cpa_commit();

#pragma unroll 1
    for (int kk = 0; kk < 16; kk += 2) {
        cpa_wait<0>();
        __syncthreads();
        if (kk + 2 < 16) {
            issue(kk + 2); cpa_commit();
            issue(kk + 3); cpa_commit();
        }
#pragma unroll
        for (int half = 0; half < 2; half++) {
            const int s = (kk + half) & 3;
            const uint4* bst = (const uint4*)(smem + (size_t)s * XP_ST + XP_B);
#pragma unroll
            for (int sub = 0; sub < 2; sub++) {
                u32 ah[2][4], al[2][4];
#pragma unroll
                for (int mt = 0; mt < 2; mt++) {
                    ldm4(ah[mt], aF[mt] + (u32)s * XP_ST + sub * 32);
                    ldm4(al[mt], aF[mt] + (u32)s * XP_ST + 10240 + sub * 32);
                }
#pragma unroll
                for (int j = 0; j < 4; j++) {
                    int f = (nq * 4 + j) * 2 + sub;
                    uint4 bp = bst[f * 32 + lane];
                    u32 bh[2] = {bp.x, bp.y}, bl[2] = {bp.z, bp.w};
#pragma unroll
                    for (int mt = 0; mt < 2; mt++) {
                        mma_f16(acc[mt][j], ah[mt], bh);
                        mma_f16(acc[mt][j], al[mt], bh);
                        mma_f16(acc[mt][j], ah[mt], bl);
                    }
                }
            }
        }
    }

#pragma unroll
    for (int mt = 0; mt < 2; mt++) {
        int rl = (wg2 * 2 + mt) * 16 + qr;
        size_t rowbase = ((size_t)mb * 128 + rl) * G4;
#pragma unroll
        for (int j = 0; j < 4; j++) {
            int col = nbx * 128 + (nq * 4 + j) * 8 + qc * 2;
            float bv0 = bih0[col] + bhh0[col];
            float bv1 = bih0[col + 1] + bhh0[col + 1];
            *(float2*)&g_xproj[rowbase + col] =
                make_float2(acc[mt][j][0] + bv0, acc[mt][j][1] + bv1);
            *(float2*)&g_xproj[rowbase + (size_t)8 * G4 + col] =
                make_float2(acc[mt][j][2] + bv0, acc[mt][j][3] + bv1);
        }
    }
}

// ===========================================================================
// Persistent fused-step kernel (fp16-only h; hi-only weights).
// Grid 128, 768 threads = 24 warps; wg = w&7 -> mtile, job = w>>3:
//   job0: h0(t+1)@Wih1 -> L1 part a; job1: h1(t)@Whh1 -> L1 part b (smem);
//   job2: h0(t+1)@Whh0 -> L0(t+1).
// Product: ah·bh. 8 MMA/chunk/warp. B prefetched across the grid barrier.
// ===========================================================================
__global__ void __launch_bounds__(768) step_persist(
    const float* __restrict__ bih1, const float* __restrict__ bhh1)
{
    extern __shared__ char smem[];
    const int tid = threadIdx.x, bx = blockIdx.x;
    const int w = tid >> 5, lane = tid & 31, qr = lane >> 2, qc = lane & 3;
    const int wg = w & 7, job = w >> 3;
    const u32 sb = smem_u32(smem);
    const int n0 = bx * 8 + qc * 2;

    // ---- prologue: L0 step 0 (h0 = 0) on this CTA's 8 columns ----
    for (int i = tid; i < 128 * 8; i += 768) {
        int m = i >> 3, u = i & 7;
        int n = bx * 8 + u;
        const float* xr = g_xproj + (size_t)m * G4;
        float iv = xr[n], gv = xr[2048 + n], ov = xr[3072 + n];
        float cn = sigm(iv) * tanhf(gv);
        g_c0[m * HID + n] = cn;
        float h = sigm(ov) * tanhf(cn);
        g_h0[1][m * HID + n] = __float2half_rn(h);
    }
    grid_barrier(0);

    // biases (L1) in regs (job0 uses them)
    float bs[4][2];
#pragma unroll
    for (int g = 0; g < 4; g++) {
        bs[g][0] = bih1[g * 1024 + n0] + bhh1[g * 1024 + n0];
        bs[g][1] = bih1[g * 1024 + n0 + 1] + bhh1[g * 1024 + n0 + 1];
    }
    // c-state in regs: job0 -> c1 (zeros), job2 -> c0 (from prologue)
    float cr[4] = {0.f, 0.f, 0.f, 0.f};
    if (job == 2) {
#pragma unroll
        for (int rr = 0; rr < 2; rr++) {
            int m = wg * 16 + qr + rr * 8;
            cr[rr * 2 + 0] = g_c0[m * HID + n0];
            cr[rr * 2 + 1] = g_c0[m * HID + n0 + 1];
        }
    }

    // ---- invariant staging coords ----
    // A: threads 0..511 stage 2 cp16 each (2 planes x 128 rows x 4 segs)
    const bool doA = (tid < 512);
    u32 adst[2]; u32 arow[2]; int aplane[2]; int aseg[2];
#pragma unroll
    for (int i = 0; i < 2; i++) {
        int idx = (tid & 511) + i * 512;
        aplane[i] = idx >> 9;
        arow[i] = (idx >> 2) & 127;
        aseg[i] = idx & 3;
        adst[i] = sb + aplane[i] * 10240 + arow[i] * 80 + aseg[i] * 16;
    }
    const int btl = tid & 255;
    const int tw = btl >> 5;
    const u32 bdst0 = sb + ST_B + (btl << 3);
    const size_t bsrc0 = (((size_t)((tw >> 1) * 128 + bx)) * 64 + (tw & 1)) * 32 + lane;
    const u32 jobAoff = (job == 1) ? 10240u : 0u;
    const u32 aF = sb + jobAoff + (wg * 16 + (lane & 15)) * 80 + ((lane >> 4) * 16);
    const int bmat = job * 256;

    float* red = (float*)smem;   // 16KB partial buffer (reuses stage 0 A area)

    auto issueB = [&](int kk) {
        const u32 soff = (u32)(kk & 3) * ST_SZ;
        cpa8(bdst0 + soff,        g_wih1p + bsrc0 + (size_t)kk * 64);
        cpa8(bdst0 + soff + 2048, g_whh1p + bsrc0 + (size_t)kk * 64);
        cpa8(bdst0 + soff + 4096, g_whh0p + bsrc0 + (size_t)kk * 64);
    };

    // initial B prefetch (chunks 0,1)
    if (!doA) {
        issueB(0); cpa_commit();
        issueB(1); cpa_commit();
    }

#pragma unroll 1
    for (int t = 0; t < STEPS; t++) {
        const int do_l0 = (t < STEPS - 1);
        const __half* Ap0 = g_h0[(t + 1) & 1];   // plane 0
        const __half* Ap1 = g_h1[t & 1];         // plane 1

        float acc[4][4];
#pragma unroll
        for (int j = 0; j < 4; j++)
#pragma unroll
            for (int k = 0; k < 4; k++) acc[j][k] = 0.f;

        auto issueA = [&](int kk) {
            const u32 soff = (u32)(kk & 3) * ST_SZ;
#pragma unroll
            for (int i = 0; i < 2; i++) {
                const __half* base = aplane[i] ? Ap1 : Ap0;
                cpa16(adst[i] + soff,
                      base + (size_t)arow[i] * HID + kk * 32 + aseg[i] * 8);
            }
        };

        if (doA) {
            issueA(0); cpa_commit();
            issueA(1); cpa_commit();
        }

#pragma unroll 1
        for (int kk = 0; kk < 32; kk += 2) {
            cpa_wait<0>();
            __syncthreads();
            if (kk + 2 < 32) {
                if (doA) issueA(kk + 2); else issueB(kk + 2);
                cpa_commit();
                if (doA) issueA(kk + 3); else issueB(kk + 3);
                cpa_commit();
            }
#pragma unroll
            for (int half = 0; half < 2; half++) {
                const int s = (kk + half) & 3;
                const u32 aBase = aF + (u32)s * ST_SZ;
                const uint2* bst = (const uint2*)(smem + (size_t)s * ST_SZ + ST_B);
#pragma unroll
                for (int sub = 0; sub < 2; sub++) {
                    u32 ah[4];
                    ldm4(ah, aBase + sub * 32);
#pragma unroll
                    for (int nt = 0; nt < 4; nt++) {
                        uint2 bp = bst[bmat + (nt * 2 + sub) * 32 + lane];
                        u32 bh[2] = {bp.x, bp.y};
                        mma_f16(acc[nt], ah, bh);
                    }
                }
            }
        }
        cpa_wait<0>();
        __syncthreads();

        // prefetch next step's B (weights step-invariant; stages 0,1 free)
        if (!doA && t + 1 < STEPS) {
            issueB(0); cpa_commit();
            issueB(1); cpa_commit();
        }

        // ---- combine: job1 publishes L1 partials ----
        if (job == 1) {
#pragma unroll
            for (int nt = 0; nt < 4; nt++)
#pragma unroll
                for (int r = 0; r < 4; r++)
                    red[(((wg * 4 + nt) * 4 + r) << 5) + lane] = acc[nt][r];
        }
        __syncthreads();

        if (job == 0) {
            // ---- L1(t) epilogue ----
            __half* H = g_h1[(t + 1) & 1];
#pragma unroll
            for (int rr = 0; rr < 2; rr++) {
                int m = wg * 16 + qr + rr * 8;
                __half hh[2];
#pragma unroll
                for (int e = 0; e < 2; e++) {
                    int ri = rr * 2 + e;
                    float pI = red[(((wg * 4 + 0) * 4 + ri) << 5) + lane];
                    float pF = red[(((wg * 4 + 1) * 4 + ri) << 5) + lane];
                    float pG = red[(((wg * 4 + 2) * 4 + ri) << 5) + lane];
                    float pO = red[(((wg * 4 + 3) * 4 + ri) << 5) + lane];
                    float iv = acc[0][ri] + pI + bs[0][e];
                    float fv = acc[1][ri] + pF + bs[1][e];
                    float gv = acc[2][ri] + pG + bs[2][e];
                    float ov = acc[3][ri] + pO + bs[3][e];
                    float cn = sigm(fv) * cr[ri] + sigm(iv) * tanhf(gv);
                    cr[ri] = cn;
                    hh[e] = __float2half_rn(sigm(ov) * tanhf(cn));
                }
                *(__half2*)&H[m * HID + n0] = __halves2half2(hh[0], hh[1]);
            }
        } else if (job == 2 && do_l0) {
            // ---- L0(t+1) epilogue ----
            const float* xp = g_xproj + (size_t)(t + 1) * BATCH * G4;
            __half* H = g_h0[t & 1];
#pragma unroll
            for (int rr = 0; rr < 2; rr++) {
                int m = wg * 16 + qr + rr * 8;
                const float* xr = xp + (size_t)m * G4 + n0;
                float2 xi = *(const float2*)(xr);
                float2 xf = *(const float2*)(xr + 1024);
                float2 xg = *(const float2*)(xr + 2048);
                float2 xo = *(const float2*)(xr + 3072);
                __half hh[2];
#pragma unroll
                for (int e = 0; e < 2; e++) {
                    int ri = rr * 2 + e;
                    float iv = acc[0][ri] + (e ? xi.y : xi.x);
                    float fv = acc[1][ri] + (e ? xf.y : xf.x);
                    float gv = acc[2][ri] + (e ? xg.y : xg.x);
                    float ov = acc[3][ri] + (e ? xo.y : xo.x);
                    float cn = sigm(fv) * cr[ri] + sigm(iv) * tanhf(gv);
                    cr[ri] = cn;
                    hh[e] = __float2half_rn(sigm(ov) * tanhf(cn));
                }
                *(__half2*)&H[m * HID + n0] = __halves2half2(hh[0], hh[1]);
            }
        }
        grid_barrier(t + 1);
    }
}

// ---------------- classifier (fp16 h) ---------------------------------------
__global__ void __launch_bounds__(256) classifier_kernel(
    const float* __restrict__ Wcls, const float* __restrict__ bcls,
    const float* __restrict__ dropu, float* __restrict__ out)
{
    int gw = (blockIdx.x * blockDim.x + threadIdx.x) >> 5;
    int lane = threadIdx.x & 31;
    int j = gw >> 5;
    int b0 = (gw & 31) * 4;
    const __half* hi = g_h1[0];   // t=63 -> buffer (63+1)&1 = 0

    float acc[4] = {0.f, 0.f, 0.f, 0.f};
#pragma unroll
    for (int it = 0; it < 8; ++it) {
        int h = it * 128 + lane * 4;
        float4 wv = *(const float4*)&Wcls[(size_t)j * HID + h];
#pragma unroll
        for (int bi = 0; bi < 4; ++bi) {
            int b = b0 + bi;
            int idx = b * HID + h;
            __half2 a0 = *(const __half2*)&hi[idx];
            __half2 a1 = *(const __half2*)&hi[idx + 2];
            float2 f0 = __half22float2(a0), f1 = __half22float2(a1);
            float4 u = *(const float4*)&dropu[(size_t)b * HID + h];
            acc[bi] += (u.x > 0.5f ? f0.x : 0.f) * wv.x
                     + (u.y > 0.5f ? f0.y : 0.f) * wv.y
                     + (u.z > 0.5f ? f1.x : 0.f) * wv.z
                     + (u.w > 0.5f ? f1.y : 0.f) * wv.w;
        }
    }
#pragma unroll
    for (int bi = 0; bi < 4; ++bi) {
        float v = acc[bi];
#pragma unroll
        for (int off = 16; off; off >>= 1)
            v += __shfl_xor_sync(0xffffffffu, v, off);
        if (lane == 0)
            out[(size_t)(b0 + bi) * 1000 + j] = 2.0f * v + bcls[j];
    }
}

// ---------------- launch ----------------------------------------------------
extern "C" void kernel_launch(void* const* d_in, const int* in_sizes, int n_in,
                              void* d_out, int out_size)
{
    const float* xs    = (const float*)d_in[0];
    const float* Wih0  = (const float*)d_in[1];
    const float* Whh0  = (const float*)d_in[2];
    const float* bih0  = (const float*)d_in[3];
    const float* bhh0  = (const float*)d_in[4];
    const float* Wih1  = (const float*)d_in[5];
    const float* Whh1  = (const float*)d_in[6];
    const float* bih1  = (const float*)d_in[7];
    const float* bhh1  = (const float*)d_in[8];
    const float* Wcls  = (const float*)d_in[9];
    const float* bcls  = (const float*)d_in[10];
    const float* dropu = (const float*)d_in[11];
    float* out = (float*)d_out;

    cudaFuncSetAttribute(step_persist, cudaFuncAttributeMaxDynamicSharedMemorySize, PS_TOTAL);
    cudaFuncSetAttribute(xproj_kernel, cudaFuncAttributeMaxDynamicSharedMemorySize, XP_TOTAL);

    init_states<<<(BATCH * HID + 255) / 256, 256>>>();
    pack_all<<<(PACK_TOTAL + 255) / 256, 256>>>(Whh0, Wih1, Whh1, Wih0, xs);
    xproj_kernel<<<dim3(32, 64), 512, XP_TOTAL>>>(bih0, bhh0);
    step_persist<<<128, 768, PS_TOTAL>>>(bih1, bhh1);
    classifier_kernel<<<4000, 256>>>(Wcls, bcls, dropu, out);
}